// round 10
// baseline (speedup 1.0000x reference)
#include <cuda_runtime.h>
#include <cuda_bf16.h>
#include <math.h>
#include <stdint.h>

// Problem constants
#define BB 4
#define TT 1024
#define EE 1024
#define HH 16
#define DD 64
#define FF 4096
#define LL 6
#define VV 32000
#define MM (BB*TT)
#define QKVW 3072
#define LN_EPS 1e-5f

// ---------------------------------------------------------------------------
// Scratch (device globals; no cudaMalloc allowed)
// ---------------------------------------------------------------------------
__device__ float g_x[(size_t)MM * EE];
__device__ float g_h[(size_t)MM * EE];
__device__ float g_qkv[(size_t)MM * QKVW];
__device__ float g_o[(size_t)MM * EE];
__device__ float g_f[(size_t)MM * FF];
// pre-rounded (tf32-in-fp32) weights
__device__ float g_wqkv[(size_t)LL * EE * QKVW];
__device__ float g_wo[(size_t)LL * EE * EE];
__device__ float g_w1[(size_t)LL * EE * FF];
__device__ float g_w2[(size_t)LL * FF * EE];
__device__ float g_wte[(size_t)VV * EE];

__device__ __forceinline__ float tf32r(float x) {
    uint32_t u;
    asm("cvt.rna.tf32.f32 %0, %1;" : "=r"(u) : "f"(x));
    return __uint_as_float(u);
}

// Fast exact-grade GELU: A&S 7.1.26 erf, |abs err| <= 1.5e-7
__device__ __forceinline__ float fast_gelu(float v) {
    float x  = v * 0.70710678118654752f;
    float ax = fabsf(x);
    float t  = 1.0f / (1.0f + 0.3275911f * ax);
    float p  = ((((1.061405429f * t - 1.453152027f) * t + 1.421413741f) * t
                 - 0.284496736f) * t + 0.254829592f) * t;
    float er = 1.0f - p * __expf(-x * x);
    er = copysignf(er, x);
    return 0.5f * v * (1.0f + er);
}

// ---------------------------------------------------------------------------
// Round-copy: out[i] = tf32(in[i])
// ---------------------------------------------------------------------------
__global__ __launch_bounds__(256) void round_copy(const float* __restrict__ in,
                                                  float* __restrict__ out, long long n4)
{
    long long i = (long long)blockIdx.x * 256 + threadIdx.x;
    if (i < n4) {
        float4 v = ((const float4*)in)[i];
        v.x = tf32r(v.x); v.y = tf32r(v.y); v.z = tf32r(v.z); v.w = tf32r(v.w);
        ((float4*)out)[i] = v;
    }
}

// Pack Wq|Wk|Wv into [L][E][3E], tf32-rounded.
__global__ __launch_bounds__(256) void pack_qkv(const float* __restrict__ Wq,
                                                const float* __restrict__ Wk,
                                                const float* __restrict__ Wv,
                                                float* __restrict__ out)
{
    long long i = (long long)blockIdx.x * 256 + threadIdx.x;   // float4 index
    const long long row_f4 = QKVW / 4;                          // 768
    long long row  = i / row_f4;                                // l*EE + kk
    int col4 = (int)(i - row * row_f4);
    int sel  = col4 / (EE / 4);
    int c    = col4 - sel * (EE / 4);
    const float* src = (sel == 0 ? Wq : sel == 1 ? Wk : Wv);
    float4 v = ((const float4*)(src + row * EE))[c];
    v.x = tf32r(v.x); v.y = tf32r(v.y); v.z = tf32r(v.z); v.w = tf32r(v.w);
    ((float4*)out)[i] = v;
}

// ---------------------------------------------------------------------------
// Embedding
// ---------------------------------------------------------------------------
__global__ void embed_kernel(const int* __restrict__ idx,
                             const float* __restrict__ wte,
                             const float* __restrict__ wpe,
                             float* __restrict__ x)
{
    long long i = (long long)blockIdx.x * blockDim.x + threadIdx.x;
    int bt = (int)(i >> 10);
    int e  = (int)(i & 1023);
    int t  = bt & (TT - 1);
    x[i] = wte[(long long)idx[bt] * EE + e] + wpe[(long long)t * EE + e];
}

// ---------------------------------------------------------------------------
// LayerNorm (output tf32-rounded; only feeds GEMMs)
// ---------------------------------------------------------------------------
__device__ __forceinline__ float warp_sum(float v) {
    #pragma unroll
    for (int o = 16; o > 0; o >>= 1) v += __shfl_xor_sync(0xffffffffu, v, o);
    return v;
}

__global__ __launch_bounds__(256) void ln_kernel(const float* __restrict__ x,
                                                 const float* __restrict__ gamma,
                                                 const float* __restrict__ beta,
                                                 float* __restrict__ out)
{
    int row = blockIdx.x;
    const float* xr = x + (long long)row * EE;
    float* orow = out + (long long)row * EE;
    int tid = threadIdx.x;

    float s = 0.f, s2 = 0.f;
    float vals[4];
    #pragma unroll
    for (int u = 0; u < 4; u++) {
        float v = xr[tid + u * 256];
        vals[u] = v;
        s += v; s2 += v * v;
    }
    s  = warp_sum(s);
    s2 = warp_sum(s2);
    __shared__ float shs[8], shs2[8];
    int wid = tid >> 5, lane = tid & 31;
    if (lane == 0) { shs[wid] = s; shs2[wid] = s2; }
    __syncthreads();
    float ts = 0.f, ts2 = 0.f;
    #pragma unroll
    for (int i = 0; i < 8; i++) { ts += shs[i]; ts2 += shs2[i]; }
    float mean = ts * (1.0f / EE);
    float var  = ts2 * (1.0f / EE) - mean * mean;
    float rstd = rsqrtf(var + LN_EPS);
    #pragma unroll
    for (int u = 0; u < 4; u++) {
        int j = tid + u * 256;
        orow[j] = tf32r((vals[u] - mean) * rstd * gamma[j] + beta[j]);
    }
}

// ---------------------------------------------------------------------------
// cp.async helpers
// ---------------------------------------------------------------------------
__device__ __forceinline__ void cpa16(uint32_t dst, const float* src) {
    asm volatile("cp.async.cg.shared.global [%0], [%1], 16;" :: "r"(dst), "l"(src));
}
__device__ __forceinline__ void cpa_commit() {
    asm volatile("cp.async.commit_group;");
}
template<int N>
__device__ __forceinline__ void cpa_wait() {
    asm volatile("cp.async.wait_group %0;" :: "n"(N));
}

__device__ __forceinline__ void mma_tf32(float* c, const uint32_t* a, const uint32_t* b) {
    asm volatile(
        "mma.sync.aligned.m16n8k8.row.col.f32.tf32.tf32.f32 "
        "{%0,%1,%2,%3}, {%4,%5,%6,%7}, {%8,%9}, {%0,%1,%2,%3};\n"
        : "+f"(c[0]), "+f"(c[1]), "+f"(c[2]), "+f"(c[3])
        : "r"(a[0]), "r"(a[1]), "r"(a[2]), "r"(a[3]), "r"(b[0]), "r"(b[1]));
}

// ---------------------------------------------------------------------------
// Fused flash attention (causal), tf32 tensor cores. (validated R7-R9)
// ---------------------------------------------------------------------------
#define KST 68
#define VST 72
#define PST 132
#define KVSTAGE (128*KST + 128*VST)
#define PS_OFF  (2*KVSTAGE)
#define FA_SMEM ((PS_OFF + 128*PST) * 4)

__global__ __launch_bounds__(256, 1) void flash_kernel(
    const float* __restrict__ QKV, float* __restrict__ O)
{
    extern __shared__ float sm[];

    int mb = gridDim.x - 1 - blockIdx.x;   // heavy blocks first
    int bh = blockIdx.y;
    int b = bh >> 4, h = bh & 15;
    int m0 = mb * 128;

    const float* Qp = QKV + (long long)b * TT * QKVW + (long long)h * DD;
    const float* Kp = Qp + EE;
    const float* Vp = Qp + 2 * EE;
    float*       Op = O + (long long)b * TT * EE + (long long)h * DD;

    int tid = threadIdx.x, warp = tid >> 5, lane = tid & 31;
    int g = lane >> 2, tg = lane & 3;

    uint32_t smem_u32 = (uint32_t)__cvta_generic_to_shared(sm);

    auto load_kv = [&](int stage, int j0) {
        uint32_t base = smem_u32 + (uint32_t)(stage * KVSTAGE) * 4u;
        #pragma unroll
        for (int i = 0; i < 8; i++) {
            int idx = tid + i * 256;
            int row = idx >> 4;
            int col = (idx & 15) << 2;
            cpa16(base + (uint32_t)(row * KST + col) * 4u,
                  Kp + (long long)(j0 + row) * QKVW + col);
        }
        #pragma unroll
        for (int i = 0; i < 8; i++) {
            int idx = tid + i * 256;
            int row = idx >> 4;
            int col = (idx & 15) << 2;
            cpa16(base + (uint32_t)(128 * KST + row * VST + col) * 4u,
                  Vp + (long long)(j0 + row) * QKVW + col);
        }
    };

    {
        uint32_t qbase = smem_u32 + (uint32_t)PS_OFF * 4u;
        #pragma unroll
        for (int i = 0; i < 8; i++) {
            int idx = tid + i * 256;
            int row = idx >> 4;
            int col = (idx & 15) << 2;
            cpa16(qbase + (uint32_t)(row * KST + col) * 4u,
                  Qp + (long long)(m0 + row) * QKVW + col);
        }
        cpa_commit();
        load_kv(0, 0);
        cpa_commit();
        cpa_wait<0>();
        __syncthreads();
    }

    uint32_t qf[8][4];
    {
        const float* Qs = sm + PS_OFF;
        #pragma unroll
        for (int kc = 0; kc < 8; kc++) {
            const float* qp2 = Qs + (warp * 16 + g) * KST + kc * 8 + tg;
            qf[kc][0] = __float_as_uint(0.125f * qp2[0]);
            qf[kc][1] = __float_as_uint(0.125f * qp2[8 * KST]);
            qf[kc][2] = __float_as_uint(0.125f * qp2[4]);
            qf[kc][3] = __float_as_uint(0.125f * qp2[8 * KST + 4]);
        }
    }
    __syncthreads();

    float m_[2] = {-1e30f, -1e30f};
    float l_[2] = {0.f, 0.f};
    float oacc[8][4];
    #pragma unroll
    for (int i = 0; i < 8; i++)
        #pragma unroll
        for (int c = 0; c < 4; c++) oacc[i][c] = 0.f;

    int nblk = mb;
    for (int jb = 0; jb <= nblk; jb++) {
        cpa_wait<0>();
        __syncthreads();
        if (jb < nblk) {
            load_kv((jb + 1) & 1, (jb + 1) * 128);
            cpa_commit();
        }

        const float* Ks = sm + (jb & 1) * KVSTAGE;
        const float* Vs = Ks + 128 * KST;

        float sacc[16][4];
        #pragma unroll
        for (int nf = 0; nf < 16; nf++)
            #pragma unroll
            for (int c = 0; c < 4; c++) sacc[nf][c] = 0.f;

        #pragma unroll
        for (int kc = 0; kc < 8; kc++) {
            #pragma unroll
            for (int nf = 0; nf < 16; nf++) {
                const float* bp = Ks + (nf * 8 + g) * KST + kc * 8 + tg;
                uint32_t bfr[2];
                bfr[0] = __float_as_uint(bp[0]);
                bfr[1] = __float_as_uint(bp[4]);
                mma_tf32(sacc[nf], qf[kc], bfr);
            }
        }

        if (jb == nblk) {
            int i0 = m0 + warp * 16 + g;
            #pragma unroll
            for (int nf = 0; nf < 16; nf++) {
                int j0c = jb * 128 + nf * 8 + 2 * tg;
                if (j0c     > i0)     sacc[nf][0] = -1e30f;
                if (j0c + 1 > i0)     sacc[nf][1] = -1e30f;
                if (j0c     > i0 + 8) sacc[nf][2] = -1e30f;
                if (j0c + 1 > i0 + 8) sacc[nf][3] = -1e30f;
            }
        }

        float rm0 = -1e30f, rm1 = -1e30f;
        #pragma unroll
        for (int nf = 0; nf < 16; nf++) {
            rm0 = fmaxf(rm0, fmaxf(sacc[nf][0], sacc[nf][1]));
            rm1 = fmaxf(rm1, fmaxf(sacc[nf][2], sacc[nf][3]));
        }
        rm0 = fmaxf(rm0, __shfl_xor_sync(0xffffffffu, rm0, 1));
        rm0 = fmaxf(rm0, __shfl_xor_sync(0xffffffffu, rm0, 2));
        rm1 = fmaxf(rm1, __shfl_xor_sync(0xffffffffu, rm1, 1));
        rm1 = fmaxf(rm1, __shfl_xor_sync(0xffffffffu, rm1, 2));

        float mn0 = fmaxf(m_[0], rm0), mn1 = fmaxf(m_[1], rm1);
        float sc0 = __expf(m_[0] - mn0), sc1 = __expf(m_[1] - mn1);
        m_[0] = mn0; m_[1] = mn1;

        float rs0 = 0.f, rs1 = 0.f;
        #pragma unroll
        for (int nf = 0; nf < 16; nf++) {
            sacc[nf][0] = __expf(sacc[nf][0] - mn0);
            sacc[nf][1] = __expf(sacc[nf][1] - mn0);
            sacc[nf][2] = __expf(sacc[nf][2] - mn1);
            sacc[nf][3] = __expf(sacc[nf][3] - mn1);
            rs0 += sacc[nf][0] + sacc[nf][1];
            rs1 += sacc[nf][2] + sacc[nf][3];
        }
        rs0 += __shfl_xor_sync(0xffffffffu, rs0, 1);
        rs0 += __shfl_xor_sync(0xffffffffu, rs0, 2);
        rs1 += __shfl_xor_sync(0xffffffffu, rs1, 1);
        rs1 += __shfl_xor_sync(0xffffffffu, rs1, 2);
        l_[0] = l_[0] * sc0 + rs0;
        l_[1] = l_[1] * sc1 + rs1;

        #pragma unroll
        for (int nf = 0; nf < 8; nf++) {
            oacc[nf][0] *= sc0; oacc[nf][1] *= sc0;
            oacc[nf][2] *= sc1; oacc[nf][3] *= sc1;
        }

        {
            float* Pw = sm + PS_OFF + (warp * 16 + g) * PST;
            #pragma unroll
            for (int nf = 0; nf < 16; nf++) {
                int c = nf * 8 + 2 * tg;
                float2 p0 = make_float2(tf32r(sacc[nf][0]), tf32r(sacc[nf][1]));
                float2 p1 = make_float2(tf32r(sacc[nf][2]), tf32r(sacc[nf][3]));
                *(float2*)(Pw + c)           = p0;
                *(float2*)(Pw + 8 * PST + c) = p1;
            }
        }
        __syncwarp();

        const float* Pr = sm + PS_OFF + (warp * 16 + g) * PST;
        #pragma unroll
        for (int kc = 0; kc < 16; kc++) {
            uint32_t afr[4];
            const float* ap = Pr + kc * 8 + tg;
            afr[0] = __float_as_uint(ap[0]);
            afr[1] = __float_as_uint(ap[8 * PST]);
            afr[2] = __float_as_uint(ap[4]);
            afr[3] = __float_as_uint(ap[8 * PST + 4]);
            #pragma unroll
            for (int nf = 0; nf < 8; nf++) {
                const float* bp = Vs + (kc * 8 + tg) * VST + nf * 8 + g;
                uint32_t bfr[2];
                bfr[0] = __float_as_uint(bp[0]);
                bfr[1] = __float_as_uint(bp[4 * VST]);
                mma_tf32(oacc[nf], afr, bfr);
            }
        }
    }

    float inv0 = 1.0f / l_[0], inv1 = 1.0f / l_[1];
    int r0 = m0 + warp * 16 + g;
    #pragma unroll
    for (int nf = 0; nf < 8; nf++) {
        int c = nf * 8 + 2 * tg;
        float* o0 = Op + (long long)r0 * EE + c;
        float* o1 = Op + (long long)(r0 + 8) * EE + c;
        *(float2*)o0 = make_float2(tf32r(oacc[nf][0] * inv0), tf32r(oacc[nf][1] * inv0));
        *(float2*)o1 = make_float2(tf32r(oacc[nf][2] * inv1), tf32r(oacc[nf][3] * inv1));
    }
}

// ---------------------------------------------------------------------------
// Tensor-core tf32 GEMM v2: BM=128, BN=256, BK=32, 3-stage cp.async.
// 256 threads = 8 warps (2 M x 4 N), warp tile 64x64 (NF=8).
// FLOP/smem-byte = 16 -> tensor-bound (smem was the R8/R9 co-bottleneck).
// Requires N % 256 == 0 (all Ns here: 1024/3072/4096/32000).
// epi: 0=store 1=gelu(acc+bias) 2=C+=acc+bias 3=C+=acc ; rnd: tf32-round store
// ---------------------------------------------------------------------------
#define BM 128
#define BN 256
#define BK 32
#define AST 36          // A smem stride (BK+4)
#define BSTN (BN + 8)   // B smem stride, NN layout
#define NSTG 3

template<bool TB>
__global__ __launch_bounds__(256, 1) void gemm_tc(
    const float* __restrict__ A, const float* __restrict__ Bm,
    const float* __restrict__ bias, float* __restrict__ C,
    int M, int N, int K, int lda, int ldb, int ldc,
    int epi, int rnd)
{
    constexpr int ASZ = BM * AST;                      // 4608 floats
    constexpr int BSZ = TB ? BN * AST : BK * BSTN;     // 9216 / 8448
    constexpr int ST  = ASZ + BSZ;

    extern __shared__ float sm[];

    int m0 = blockIdx.x * BM;
    int n0 = blockIdx.y * BN;

    int nt = K / BK;

    int tid  = threadIdx.x;
    int warp = tid >> 5, lane = tid & 31;
    int g  = lane >> 2;
    int tg = lane & 3;
    int warp_m = warp >> 2;       // 0..1
    int warp_n = warp & 3;        // 0..3
    constexpr int NF = 8;         // 8 n-frags of 8 -> warp n-tile 64
    constexpr int WN = 64;

    uint32_t smem_u32 = (uint32_t)__cvta_generic_to_shared(sm);

    auto load_tiles = [&](int st, int k0) {
        uint32_t sb = smem_u32 + (uint32_t)(st * ST) * 4u;
        // A: 128x32 = 1024 float4, 4 per thread
        #pragma unroll
        for (int i = 0; i < 4; i++) {
            int idx = tid + i * 256;
            int row = idx >> 3;
            int kc  = (idx & 7) << 2;
            cpa16(sb + (uint32_t)(row * AST + kc) * 4u,
                  A + (long long)(m0 + row) * lda + k0 + kc);
        }
        if (!TB) {
            // B: 32 x 256 = 2048 float4, 8 per thread
            #pragma unroll
            for (int i = 0; i < 8; i++) {
                int idx = tid + i * 256;
                int row = idx >> 6;            // /64
                int nc  = (idx & 63) << 2;
                cpa16(sb + (uint32_t)(ASZ + row * BSTN + nc) * 4u,
                      Bm + (long long)(k0 + row) * ldb + n0 + nc);
            }
        } else {
            // B: 256 x 32 = 2048 float4, 8 per thread
            #pragma unroll
            for (int i = 0; i < 8; i++) {
                int idx = tid + i * 256;
                int row = idx >> 3;
                int kc  = (idx & 7) << 2;
                cpa16(sb + (uint32_t)(ASZ + row * AST + kc) * 4u,
                      Bm + (long long)(n0 + row) * ldb + k0 + kc);
            }
        }
    };

    float acc[4][NF][4];
    #pragma unroll
    for (int i = 0; i < 4; i++)
        #pragma unroll
        for (int j = 0; j < NF; j++)
            #pragma unroll
            for (int c = 0; c < 4; c++) acc[i][j][c] = 0.f;

    // prologue: stages 0,1 (uniform group counts)
    load_tiles(0, 0);
    cpa_commit();
    if (nt > 1) load_tiles(1, BK);
    cpa_commit();

    int cs = 0;
    int ps = 2;
    for (int it = 0; it < nt; it++) {
        cpa_wait<1>();
        __syncthreads();
        if (it + 2 < nt) load_tiles(ps, (it + 2) * BK);
        cpa_commit();

        const float* Ab = sm + cs * ST;
        const float* Bb = Ab + ASZ;

        #pragma unroll
        for (int ks = 0; ks < BK; ks += 8) {
            uint32_t afr[4][4];
            #pragma unroll
            for (int mi = 0; mi < 4; mi++) {
                const float* ap = Ab + (warp_m * 64 + mi * 16 + g) * AST + ks + tg;
                afr[mi][0] = __float_as_uint(ap[0]);
                afr[mi][1] = __float_as_uint(ap[8 * AST]);
                afr[mi][2] = __float_as_uint(ap[4]);
                afr[mi][3] = __float_as_uint(ap[8 * AST + 4]);
            }
            #pragma unroll
            for (int ni = 0; ni < NF; ni++) {
                uint32_t bfr[2];
                if (TB) {
                    const float* bp = Bb + (warp_n * WN + ni * 8 + g) * AST + ks + tg;
                    bfr[0] = __float_as_uint(bp[0]);
                    bfr[1] = __float_as_uint(bp[4]);
                } else {
                    const float* bp = Bb + (ks + tg) * BSTN + warp_n * WN + ni * 8 + g;
                    bfr[0] = __float_as_uint(bp[0]);
                    bfr[1] = __float_as_uint(bp[4 * BSTN]);
                }
                #pragma unroll
                for (int mi = 0; mi < 4; mi++)
                    mma_tf32(acc[mi][ni], afr[mi], bfr);
            }
        }

        cs++; if (cs == NSTG) cs = 0;
        ps++; if (ps == NSTG) ps = 0;
    }

    // epilogue (float2 per row-pair)
    #pragma unroll
    for (int mi = 0; mi < 4; mi++) {
        #pragma unroll
        for (int ni = 0; ni < NF; ni++) {
            int r0 = m0 + warp_m * 64 + mi * 16 + g;
            int c0 = n0 + warp_n * WN + ni * 8 + 2 * tg;
            #pragma unroll
            for (int p = 0; p < 2; p++) {
                int m = r0 + p * 8;
                float vx = acc[mi][ni][2 * p];
                float vy = acc[mi][ni][2 * p + 1];
                float* cp = C + (long long)m * ldc + c0;
                if (epi == 1) {
                    vx = fast_gelu(vx + bias[c0]);
                    vy = fast_gelu(vy + bias[c0 + 1]);
                } else if (epi == 2) {
                    float2 old = *(const float2*)cp;
                    vx += bias[c0]     + old.x;
                    vy += bias[c0 + 1] + old.y;
                } else if (epi == 3) {
                    float2 old = *(const float2*)cp;
                    vx += old.x;
                    vy += old.y;
                }
                if (rnd) { vx = tf32r(vx); vy = tf32r(vy); }
                *(float2*)cp = make_float2(vx, vy);
            }
        }
    }
}

// ---------------------------------------------------------------------------
// Host-side launch helper (N must be divisible by 256)
// ---------------------------------------------------------------------------
static inline void gemm(const float* A, const float* B, const float* bias, float* C,
                        int M, int N, int K, int lda, int ldb, int ldc, bool tb,
                        int epi, int rnd)
{
    dim3 block(256);
    dim3 grid(M / BM, N / BN);
    constexpr int ASZ = BM * AST;
    if (tb) {
        size_t bytes = (size_t)NSTG * (ASZ + BN * AST) * 4;
        gemm_tc<true><<<grid, block, bytes>>>(A, B, bias, C, M, N, K,
                                              lda, ldb, ldc, epi, rnd);
    } else {
        size_t bytes = (size_t)NSTG * (ASZ + BK * BSTN) * 4;
        gemm_tc<false><<<grid, block, bytes>>>(A, B, bias, C, M, N, K,
                                               lda, ldb, ldc, epi, rnd);
    }
}

extern "C" void kernel_launch(void* const* d_in, const int* in_sizes, int n_in,
                              void* d_out, int out_size)
{
    (void)in_sizes; (void)n_in; (void)out_size;
    const int*   idx  = (const int*)  d_in[0];
    const float* wte  = (const float*)d_in[1];
    const float* wpe  = (const float*)d_in[2];
    const float* Wq   = (const float*)d_in[3];
    const float* Wk   = (const float*)d_in[4];
    const float* Wv   = (const float*)d_in[5];
    const float* Wo   = (const float*)d_in[6];
    const float* ln1g = (const float*)d_in[7];
    const float* ln1b = (const float*)d_in[8];
    const float* ln2g = (const float*)d_in[9];
    const float* ln2b = (const float*)d_in[10];
    const float* W1   = (const float*)d_in[11];
    const float* b1   = (const float*)d_in[12];
    const float* W2   = (const float*)d_in[13];
    const float* b2   = (const float*)d_in[14];
    const float* lnfg = (const float*)d_in[15];
    const float* lnfb = (const float*)d_in[16];
    float* out = (float*)d_out;

    float *x, *h, *qkv, *o, *f;
    float *wqkv, *wo, *w1, *w2, *wt;
    cudaGetSymbolAddress((void**)&x, g_x);
    cudaGetSymbolAddress((void**)&h, g_h);
    cudaGetSymbolAddress((void**)&qkv, g_qkv);
    cudaGetSymbolAddress((void**)&o, g_o);
    cudaGetSymbolAddress((void**)&f, g_f);
    cudaGetSymbolAddress((void**)&wqkv, g_wqkv);
    cudaGetSymbolAddress((void**)&wo, g_wo);
    cudaGetSymbolAddress((void**)&w1, g_w1);
    cudaGetSymbolAddress((void**)&w2, g_w2);
    cudaGetSymbolAddress((void**)&wt, g_wte);

    cudaFuncSetAttribute(gemm_tc<true >, cudaFuncAttributeMaxDynamicSharedMemorySize, 200 * 1024);
    cudaFuncSetAttribute(gemm_tc<false>, cudaFuncAttributeMaxDynamicSharedMemorySize, 200 * 1024);
    cudaFuncSetAttribute(flash_kernel, cudaFuncAttributeMaxDynamicSharedMemorySize, FA_SMEM);

    // pack + pre-round weights to tf32
    {
        long long nqkv = (long long)LL * EE * QKVW / 4;
        pack_qkv<<<(unsigned)((nqkv + 255) / 256), 256>>>(Wq, Wk, Wv, wqkv);
        long long nqk = (long long)LL * EE * EE / 4;
        round_copy<<<(unsigned)((nqk + 255) / 256), 256>>>(Wo, wo, nqk);
        long long nff = (long long)LL * EE * FF / 4;
        round_copy<<<(unsigned)((nff + 255) / 256), 256>>>(W1, w1, nff);
        round_copy<<<(unsigned)((nff + 255) / 256), 256>>>(W2, w2, nff);
        long long nte = (long long)VV * EE / 4;
        round_copy<<<(unsigned)((nte + 255) / 256), 256>>>(wte, wt, nte);
    }

    embed_kernel<<<(MM * EE) / 256, 256>>>(idx, wte, wpe, x);

    for (int l = 0; l < LL; l++) {
        ln_kernel<<<MM, 256>>>(x, ln1g + (long long)l * EE, ln1b + (long long)l * EE, h);

        // fused QKV projection: [4096 x 3072] = h @ WqkvPacked
        gemm(h, wqkv + (long long)l * EE * QKVW, nullptr, qkv,
             MM, QKVW, EE, EE, QKVW, QKVW, false, 0, 1);

        // fused causal attention
        {
            dim3 grid(TT / 128, BB * HH);
            flash_kernel<<<grid, 256, FA_SMEM>>>(qkv, o);
        }

        gemm(o, wo + (long long)l * EE * EE, nullptr, x,
             MM, EE, EE, EE, EE, EE, false, 3, 0);

        ln_kernel<<<MM, 256>>>(x, ln2g + (long long)l * EE, ln2b + (long long)l * EE, h);

        gemm(h, w1 + (long long)l * EE * FF, b1 + (long long)l * FF, f,
             MM, FF, EE, EE, FF, FF, false, 1, 1);

        gemm(f, w2 + (long long)l * FF * EE, b2 + (long long)l * EE, x,
             MM, EE, FF, FF, EE, EE, false, 2, 0);
    }

    ln_kernel<<<MM, 256>>>(x, lnfg, lnfb, h);

    gemm(h, wt, nullptr, out, MM, VV, EE, EE, EE, VV, true, 0, 0);
}

// round 11
// speedup vs baseline: 1.5306x; 1.5306x over previous
#include <cuda_runtime.h>
#include <cuda_bf16.h>
#include <cuda_fp16.h>
#include <math.h>
#include <stdint.h>

// Problem constants
#define BB 4
#define TT 1024
#define EE 1024
#define HH 16
#define DD 64
#define FF 4096
#define LL 6
#define VV 32000
#define MM (BB*TT)
#define QKVW 3072
#define LN_EPS 1e-5f

// ---------------------------------------------------------------------------
// Scratch (device globals; no cudaMalloc allowed)
// ---------------------------------------------------------------------------
__device__ float g_x[(size_t)MM * EE];                       // residual (fp32)
__device__ __align__(16) __half g_h[(size_t)MM * EE];        // LN out (fp16)
__device__ float g_qkv[(size_t)MM * QKVW];                   // QKV (fp32, flash input)
__device__ __align__(16) __half g_o[(size_t)MM * EE];        // attn out (fp16)
__device__ __align__(16) __half g_f[(size_t)MM * FF];        // FFN mid (fp16)
// fp16 weights, all stored [N][K] (transposed where needed)
__device__ __align__(16) __half g_wqkv[(size_t)LL * QKVW * EE];
__device__ __align__(16) __half g_wo[(size_t)LL * EE * EE];
__device__ __align__(16) __half g_w1[(size_t)LL * FF * EE];
__device__ __align__(16) __half g_w2[(size_t)LL * EE * FF];
__device__ __align__(16) __half g_wte[(size_t)VV * EE];

__device__ __forceinline__ float tf32r(float x) {
    uint32_t u;
    asm("cvt.rna.tf32.f32 %0, %1;" : "=r"(u) : "f"(x));
    return __uint_as_float(u);
}

// Fast exact-grade GELU: A&S 7.1.26 erf, |abs err| <= 1.5e-7
__device__ __forceinline__ float fast_gelu(float v) {
    float x  = v * 0.70710678118654752f;
    float ax = fabsf(x);
    float t  = 1.0f / (1.0f + 0.3275911f * ax);
    float p  = ((((1.061405429f * t - 1.453152027f) * t + 1.421413741f) * t
                 - 0.284496736f) * t + 0.254829592f) * t;
    float er = 1.0f - p * __expf(-x * x);
    er = copysignf(er, x);
    return 0.5f * v * (1.0f + er);
}

// ---------------------------------------------------------------------------
// Weight prep: transpose fp32 [K][N] -> fp16 [N][K]  (per layer z)
// ---------------------------------------------------------------------------
__global__ __launch_bounds__(256) void transpose_half(const float* __restrict__ in,
                                                      __half* __restrict__ out,
                                                      int K, int N)
{
    __shared__ float t[32][33];
    int l = blockIdx.z;
    in  += (size_t)l * K * N;
    out += (size_t)l * K * N;
    int n0 = blockIdx.x * 32, k0 = blockIdx.y * 32;
    int tx = threadIdx.x & 31, ty = threadIdx.x >> 5;   // 32 x 8
    #pragma unroll
    for (int j = 0; j < 4; j++)
        t[ty + 8 * j][tx] = in[(size_t)(k0 + ty + 8 * j) * N + n0 + tx];
    __syncthreads();
    #pragma unroll
    for (int j = 0; j < 4; j++)
        out[(size_t)(n0 + ty + 8 * j) * K + k0 + tx] = __float2half(t[tx][ty + 8 * j]);
}

// Pack+transpose Wq|Wk|Wv [L][E][E] -> [L][3E][E] fp16
__global__ __launch_bounds__(256) void transpose_qkv(const float* __restrict__ Wq,
                                                     const float* __restrict__ Wk,
                                                     const float* __restrict__ Wv,
                                                     __half* __restrict__ out)
{
    __shared__ float t[32][33];
    int l = blockIdx.z;
    int n0 = blockIdx.x * 32, k0 = blockIdx.y * 32;
    int sel = n0 >> 10;            // 0..2 (1024 % 32 == 0)
    int nn0 = n0 & 1023;
    const float* src = (sel == 0 ? Wq : sel == 1 ? Wk : Wv) + (size_t)l * EE * EE;
    int tx = threadIdx.x & 31, ty = threadIdx.x >> 5;
    #pragma unroll
    for (int j = 0; j < 4; j++)
        t[ty + 8 * j][tx] = src[(size_t)(k0 + ty + 8 * j) * EE + nn0 + tx];
    __syncthreads();
    #pragma unroll
    for (int j = 0; j < 4; j++)
        out[((size_t)l * QKVW + n0 + ty + 8 * j) * EE + k0 + tx]
            = __float2half(t[tx][ty + 8 * j]);
}

// Elementwise fp32 -> fp16 (wte: already [N][K])
__global__ __launch_bounds__(256) void conv_half(const float* __restrict__ in,
                                                 __half* __restrict__ out, long long n2)
{
    long long i = (long long)blockIdx.x * 256 + threadIdx.x;
    if (i < n2) {
        float2 v = ((const float2*)in)[i];
        ((half2*)out)[i] = __float22half2_rn(v);
    }
}

// ---------------------------------------------------------------------------
// Embedding
// ---------------------------------------------------------------------------
__global__ void embed_kernel(const int* __restrict__ idx,
                             const float* __restrict__ wte,
                             const float* __restrict__ wpe,
                             float* __restrict__ x)
{
    long long i = (long long)blockIdx.x * blockDim.x + threadIdx.x;
    int bt = (int)(i >> 10);
    int e  = (int)(i & 1023);
    int t  = bt & (TT - 1);
    x[i] = wte[(long long)idx[bt] * EE + e] + wpe[(long long)t * EE + e];
}

// ---------------------------------------------------------------------------
// LayerNorm: fp32 in, fp16 out (only feeds GEMMs)
// ---------------------------------------------------------------------------
__device__ __forceinline__ float warp_sum(float v) {
    #pragma unroll
    for (int o = 16; o > 0; o >>= 1) v += __shfl_xor_sync(0xffffffffu, v, o);
    return v;
}

__global__ __launch_bounds__(256) void ln_kernel(const float* __restrict__ x,
                                                 const float* __restrict__ gamma,
                                                 const float* __restrict__ beta,
                                                 __half* __restrict__ out)
{
    int row = blockIdx.x;
    const float* xr = x + (long long)row * EE;
    __half* orow = out + (long long)row * EE;
    int tid = threadIdx.x;

    float s = 0.f, s2 = 0.f;
    float vals[4];
    #pragma unroll
    for (int u = 0; u < 4; u++) {
        float v = xr[tid + u * 256];
        vals[u] = v;
        s += v; s2 += v * v;
    }
    s  = warp_sum(s);
    s2 = warp_sum(s2);
    __shared__ float shs[8], shs2[8];
    int wid = tid >> 5, lane = tid & 31;
    if (lane == 0) { shs[wid] = s; shs2[wid] = s2; }
    __syncthreads();
    float ts = 0.f, ts2 = 0.f;
    #pragma unroll
    for (int i = 0; i < 8; i++) { ts += shs[i]; ts2 += shs2[i]; }
    float mean = ts * (1.0f / EE);
    float var  = ts2 * (1.0f / EE) - mean * mean;
    float rstd = rsqrtf(var + LN_EPS);
    #pragma unroll
    for (int u = 0; u < 4; u++) {
        int j = tid + u * 256;
        orow[j] = __float2half((vals[u] - mean) * rstd * gamma[j] + beta[j]);
    }
}

// ---------------------------------------------------------------------------
// cp.async helpers
// ---------------------------------------------------------------------------
__device__ __forceinline__ void cpa16(uint32_t dst, const void* src) {
    asm volatile("cp.async.cg.shared.global [%0], [%1], 16;" :: "r"(dst), "l"(src));
}
__device__ __forceinline__ void cpa_commit() {
    asm volatile("cp.async.commit_group;");
}
template<int N>
__device__ __forceinline__ void cpa_wait() {
    asm volatile("cp.async.wait_group %0;" :: "n"(N));
}

__device__ __forceinline__ void mma_tf32(float* c, const uint32_t* a, const uint32_t* b) {
    asm volatile(
        "mma.sync.aligned.m16n8k8.row.col.f32.tf32.tf32.f32 "
        "{%0,%1,%2,%3}, {%4,%5,%6,%7}, {%8,%9}, {%0,%1,%2,%3};\n"
        : "+f"(c[0]), "+f"(c[1]), "+f"(c[2]), "+f"(c[3])
        : "r"(a[0]), "r"(a[1]), "r"(a[2]), "r"(a[3]), "r"(b[0]), "r"(b[1]));
}

__device__ __forceinline__ void mma_f16(float* c, const uint32_t* a, const uint32_t* b) {
    asm volatile(
        "mma.sync.aligned.m16n8k16.row.col.f32.f16.f16.f32 "
        "{%0,%1,%2,%3}, {%4,%5,%6,%7}, {%8,%9}, {%0,%1,%2,%3};\n"
        : "+f"(c[0]), "+f"(c[1]), "+f"(c[2]), "+f"(c[3])
        : "r"(a[0]), "r"(a[1]), "r"(a[2]), "r"(a[3]), "r"(b[0]), "r"(b[1]));
}

// ---------------------------------------------------------------------------
// Fused flash attention (causal), tf32 tensor cores. (validated R7-R9)
// Reads fp32 QKV; writes fp16 O.
// ---------------------------------------------------------------------------
#define KST 68
#define VST 72
#define PST 132
#define KVSTAGE (128*KST + 128*VST)
#define PS_OFF  (2*KVSTAGE)
#define FA_SMEM ((PS_OFF + 128*PST) * 4)

__global__ __launch_bounds__(256, 1) void flash_kernel(
    const float* __restrict__ QKV, __half* __restrict__ O)
{
    extern __shared__ float sm[];

    int mb = gridDim.x - 1 - blockIdx.x;   // heavy blocks first
    int bh = blockIdx.y;
    int b = bh >> 4, h = bh & 15;
    int m0 = mb * 128;

    const float* Qp = QKV + (long long)b * TT * QKVW + (long long)h * DD;
    const float* Kp = Qp + EE;
    const float* Vp = Qp + 2 * EE;
    __half*      Op = O + (long long)b * TT * EE + (long long)h * DD;

    int tid = threadIdx.x, warp = tid >> 5, lane = tid & 31;
    int g = lane >> 2, tg = lane & 3;

    uint32_t smem_u32 = (uint32_t)__cvta_generic_to_shared(sm);

    auto load_kv = [&](int stage, int j0) {
        uint32_t base = smem_u32 + (uint32_t)(stage * KVSTAGE) * 4u;
        #pragma unroll
        for (int i = 0; i < 8; i++) {
            int idx = tid + i * 256;
            int row = idx >> 4;
            int col = (idx & 15) << 2;
            cpa16(base + (uint32_t)(row * KST + col) * 4u,
                  Kp + (long long)(j0 + row) * QKVW + col);
        }
        #pragma unroll
        for (int i = 0; i < 8; i++) {
            int idx = tid + i * 256;
            int row = idx >> 4;
            int col = (idx & 15) << 2;
            cpa16(base + (uint32_t)(128 * KST + row * VST + col) * 4u,
                  Vp + (long long)(j0 + row) * QKVW + col);
        }
    };

    {
        uint32_t qbase = smem_u32 + (uint32_t)PS_OFF * 4u;
        #pragma unroll
        for (int i = 0; i < 8; i++) {
            int idx = tid + i * 256;
            int row = idx >> 4;
            int col = (idx & 15) << 2;
            cpa16(qbase + (uint32_t)(row * KST + col) * 4u,
                  Qp + (long long)(m0 + row) * QKVW + col);
        }
        cpa_commit();
        load_kv(0, 0);
        cpa_commit();
        cpa_wait<0>();
        __syncthreads();
    }

    uint32_t qf[8][4];
    {
        const float* Qs = sm + PS_OFF;
        #pragma unroll
        for (int kc = 0; kc < 8; kc++) {
            const float* qp2 = Qs + (warp * 16 + g) * KST + kc * 8 + tg;
            qf[kc][0] = __float_as_uint(0.125f * qp2[0]);
            qf[kc][1] = __float_as_uint(0.125f * qp2[8 * KST]);
            qf[kc][2] = __float_as_uint(0.125f * qp2[4]);
            qf[kc][3] = __float_as_uint(0.125f * qp2[8 * KST + 4]);
        }
    }
    __syncthreads();

    float m_[2] = {-1e30f, -1e30f};
    float l_[2] = {0.f, 0.f};
    float oacc[8][4];
    #pragma unroll
    for (int i = 0; i < 8; i++)
        #pragma unroll
        for (int c = 0; c < 4; c++) oacc[i][c] = 0.f;

    int nblk = mb;
    for (int jb = 0; jb <= nblk; jb++) {
        cpa_wait<0>();
        __syncthreads();
        if (jb < nblk) {
            load_kv((jb + 1) & 1, (jb + 1) * 128);
            cpa_commit();
        }

        const float* Ks = sm + (jb & 1) * KVSTAGE;
        const float* Vs = Ks + 128 * KST;

        float sacc[16][4];
        #pragma unroll
        for (int nf = 0; nf < 16; nf++)
            #pragma unroll
            for (int c = 0; c < 4; c++) sacc[nf][c] = 0.f;

        #pragma unroll
        for (int kc = 0; kc < 8; kc++) {
            #pragma unroll
            for (int nf = 0; nf < 16; nf++) {
                const float* bp = Ks + (nf * 8 + g) * KST + kc * 8 + tg;
                uint32_t bfr[2];
                bfr[0] = __float_as_uint(bp[0]);
                bfr[1] = __float_as_uint(bp[4]);
                mma_tf32(sacc[nf], qf[kc], bfr);
            }
        }

        if (jb == nblk) {
            int i0 = m0 + warp * 16 + g;
            #pragma unroll
            for (int nf = 0; nf < 16; nf++) {
                int j0c = jb * 128 + nf * 8 + 2 * tg;
                if (j0c     > i0)     sacc[nf][0] = -1e30f;
                if (j0c + 1 > i0)     sacc[nf][1] = -1e30f;
                if (j0c     > i0 + 8) sacc[nf][2] = -1e30f;
                if (j0c + 1 > i0 + 8) sacc[nf][3] = -1e30f;
            }
        }

        float rm0 = -1e30f, rm1 = -1e30f;
        #pragma unroll
        for (int nf = 0; nf < 16; nf++) {
            rm0 = fmaxf(rm0, fmaxf(sacc[nf][0], sacc[nf][1]));
            rm1 = fmaxf(rm1, fmaxf(sacc[nf][2], sacc[nf][3]));
        }
        rm0 = fmaxf(rm0, __shfl_xor_sync(0xffffffffu, rm0, 1));
        rm0 = fmaxf(rm0, __shfl_xor_sync(0xffffffffu, rm0, 2));
        rm1 = fmaxf(rm1, __shfl_xor_sync(0xffffffffu, rm1, 1));
        rm1 = fmaxf(rm1, __shfl_xor_sync(0xffffffffu, rm1, 2));

        float mn0 = fmaxf(m_[0], rm0), mn1 = fmaxf(m_[1], rm1);
        float sc0 = __expf(m_[0] - mn0), sc1 = __expf(m_[1] - mn1);
        m_[0] = mn0; m_[1] = mn1;

        float rs0 = 0.f, rs1 = 0.f;
        #pragma unroll
        for (int nf = 0; nf < 16; nf++) {
            sacc[nf][0] = __expf(sacc[nf][0] - mn0);
            sacc[nf][1] = __expf(sacc[nf][1] - mn0);
            sacc[nf][2] = __expf(sacc[nf][2] - mn1);
            sacc[nf][3] = __expf(sacc[nf][3] - mn1);
            rs0 += sacc[nf][0] + sacc[nf][1];
            rs1 += sacc[nf][2] + sacc[nf][3];
        }
        rs0 += __shfl_xor_sync(0xffffffffu, rs0, 1);
        rs0 += __shfl_xor_sync(0xffffffffu, rs0, 2);
        rs1 += __shfl_xor_sync(0xffffffffu, rs1, 1);
        rs1 += __shfl_xor_sync(0xffffffffu, rs1, 2);
        l_[0] = l_[0] * sc0 + rs0;
        l_[1] = l_[1] * sc1 + rs1;

        #pragma unroll
        for (int nf = 0; nf < 8; nf++) {
            oacc[nf][0] *= sc0; oacc[nf][1] *= sc0;
            oacc[nf][2] *= sc1; oacc[nf][3] *= sc1;
        }

        {
            float* Pw = sm + PS_OFF + (warp * 16 + g) * PST;
            #pragma unroll
            for (int nf = 0; nf < 16; nf++) {
                int c = nf * 8 + 2 * tg;
                float2 p0 = make_float2(tf32r(sacc[nf][0]), tf32r(sacc[nf][1]));
                float2 p1 = make_float2(tf32r(sacc[nf][2]), tf32r(sacc[nf][3]));
                *(float2*)(Pw + c)           = p0;
                *(float2*)(Pw + 8 * PST + c) = p1;
            }
        }
        __syncwarp();

        const float* Pr = sm + PS_OFF + (warp * 16 + g) * PST;
        #pragma unroll
        for (int kc = 0; kc < 16; kc++) {
            uint32_t afr[4];
            const float* ap = Pr + kc * 8 + tg;
            afr[0] = __float_as_uint(ap[0]);
            afr[1] = __float_as_uint(ap[8 * PST]);
            afr[2] = __float_as_uint(ap[4]);
            afr[3] = __float_as_uint(ap[8 * PST + 4]);
            #pragma unroll
            for (int nf = 0; nf < 8; nf++) {
                const float* bp = Vs + (kc * 8 + tg) * VST + nf * 8 + g;
                uint32_t bfr[2];
                bfr[0] = __float_as_uint(bp[0]);
                bfr[1] = __float_as_uint(bp[4 * VST]);
                mma_tf32(oacc[nf], afr, bfr);
            }
        }
    }

    float inv0 = 1.0f / l_[0], inv1 = 1.0f / l_[1];
    int r0 = m0 + warp * 16 + g;
    #pragma unroll
    for (int nf = 0; nf < 8; nf++) {
        int c = nf * 8 + 2 * tg;
        __half* o0 = Op + (long long)r0 * EE + c;
        __half* o1 = Op + (long long)(r0 + 8) * EE + c;
        *(half2*)o0 = __float22half2_rn(make_float2(oacc[nf][0] * inv0, oacc[nf][1] * inv0));
        *(half2*)o1 = __float22half2_rn(make_float2(oacc[nf][2] * inv1, oacc[nf][3] * inv1));
    }
}

// ---------------------------------------------------------------------------
// fp16 tensor-core GEMM: C[M,N] = epi( A[M,K]h @ B[N,K]h^T ), fp32 accumulate.
// BM=128, BN=128, BK=32, 3-stage cp.async (wait<1>), 8 warps (2M x 4N),
// warp tile 64x32, mma m16n8k16. B ALWAYS [N][K] (weights pre-transposed).
// epi: 0=store f32  1=gelu(acc+bias)->HALF  2=C+=acc+bias (f32)  3=C+=acc (f32)
// rnd: tf32-round the f32 store (for flash input).
// ---------------------------------------------------------------------------
#define BM 128
#define BN 128
#define BK 32
#define ASTH 40        // smem stride in halves (BK + 8)
#define NSTG 3

__global__ __launch_bounds__(256, 2) void gemm_f16(
    const __half* __restrict__ A, const __half* __restrict__ Bm,
    const float* __restrict__ bias, void* __restrict__ Cv,
    int M, int N, int K, int lda, int ldb, int ldc,
    int epi, int rnd)
{
    constexpr int ASZ = BM * ASTH;      // 5120 halves
    constexpr int BSZ = BN * ASTH;      // 5120 halves
    constexpr int ST  = ASZ + BSZ;      // 10240 halves = 20KB/stage

    extern __shared__ __half smh[];

    int m0 = blockIdx.x * BM;
    int n0 = blockIdx.y * BN;
    int nt = K / BK;

    int tid  = threadIdx.x;
    int warp = tid >> 5, lane = tid & 31;
    int g  = lane >> 2;
    int tg = lane & 3;
    int warp_m = warp >> 2;    // 0..1
    int warp_n = warp & 3;     // 0..3

    uint32_t smem_u32 = (uint32_t)__cvta_generic_to_shared(smh);

    auto load_tiles = [&](int st, int k0) {
        uint32_t sb = smem_u32 + (uint32_t)(st * ST) * 2u;
        // A: 128 rows x 32 halves = 512 x 16B chunks, 2 per thread
        #pragma unroll
        for (int i = 0; i < 2; i++) {
            int idx = tid + i * 256;
            int row = idx >> 2;
            int kc  = (idx & 3) << 3;   // halves
            cpa16(sb + (uint32_t)(row * ASTH + kc) * 2u,
                  A + (long long)(m0 + row) * lda + k0 + kc);
        }
        // B: 128 rows x 32 halves
        #pragma unroll
        for (int i = 0; i < 2; i++) {
            int idx = tid + i * 256;
            int row = idx >> 2;
            int kc  = (idx & 3) << 3;
            cpa16(sb + (uint32_t)(ASZ + row * ASTH + kc) * 2u,
                  Bm + (long long)(n0 + row) * ldb + k0 + kc);
        }
    };

    float acc[4][4][4];
    #pragma unroll
    for (int i = 0; i < 4; i++)
        #pragma unroll
        for (int j = 0; j < 4; j++)
            #pragma unroll
            for (int c = 0; c < 4; c++) acc[i][j][c] = 0.f;

    // prologue: stages 0,1
    load_tiles(0, 0);
    cpa_commit();
    if (nt > 1) load_tiles(1, BK);
    cpa_commit();

    int cs = 0, ps = 2;
    for (int it = 0; it < nt; it++) {
        cpa_wait<1>();
        __syncthreads();
        if (it + 2 < nt) load_tiles(ps, (it + 2) * BK);
        cpa_commit();

        const __half* Ab = smh + cs * ST;
        const __half* Bb = Ab + ASZ;

        #pragma unroll
        for (int ks = 0; ks < BK; ks += 16) {
            uint32_t afr[4][4];
            #pragma unroll
            for (int mi = 0; mi < 4; mi++) {
                const __half* ap = Ab + (warp_m * 64 + mi * 16 + g) * ASTH + ks + 2 * tg;
                afr[mi][0] = *(const uint32_t*)(ap);
                afr[mi][1] = *(const uint32_t*)(ap + 8 * ASTH);
                afr[mi][2] = *(const uint32_t*)(ap + 8);
                afr[mi][3] = *(const uint32_t*)(ap + 8 * ASTH + 8);
            }
            #pragma unroll
            for (int ni = 0; ni < 4; ni++) {
                const __half* bp = Bb + (warp_n * 32 + ni * 8 + g) * ASTH + ks + 2 * tg;
                uint32_t bfr[2];
                bfr[0] = *(const uint32_t*)(bp);
                bfr[1] = *(const uint32_t*)(bp + 8);
                #pragma unroll
                for (int mi = 0; mi < 4; mi++)
                    mma_f16(acc[mi][ni], afr[mi], bfr);
            }
        }

        cs++; if (cs == NSTG) cs = 0;
        ps++; if (ps == NSTG) ps = 0;
    }

    // epilogue
    #pragma unroll
    for (int mi = 0; mi < 4; mi++) {
        #pragma unroll
        for (int ni = 0; ni < 4; ni++) {
            int r0 = m0 + warp_m * 64 + mi * 16 + g;
            int c0 = n0 + warp_n * 32 + ni * 8 + 2 * tg;
            #pragma unroll
            for (int p = 0; p < 2; p++) {
                int m = r0 + p * 8;
                float vx = acc[mi][ni][2 * p];
                float vy = acc[mi][ni][2 * p + 1];
                if (epi == 1) {
                    vx = fast_gelu(vx + bias[c0]);
                    vy = fast_gelu(vy + bias[c0 + 1]);
                    __half* cp = (__half*)Cv + (long long)m * ldc + c0;
                    *(half2*)cp = __float22half2_rn(make_float2(vx, vy));
                } else {
                    float* cp = (float*)Cv + (long long)m * ldc + c0;
                    if (epi == 2) {
                        float2 old = *(const float2*)cp;
                        vx += bias[c0]     + old.x;
                        vy += bias[c0 + 1] + old.y;
                    } else if (epi == 3) {
                        float2 old = *(const float2*)cp;
                        vx += old.x;
                        vy += old.y;
                    }
                    if (rnd) { vx = tf32r(vx); vy = tf32r(vy); }
                    *(float2*)cp = make_float2(vx, vy);
                }
            }
        }
    }
}

// ---------------------------------------------------------------------------
// Host-side launch helper
// ---------------------------------------------------------------------------
static inline void gemm(const __half* A, const __half* B, const float* bias, void* C,
                        int M, int N, int K, int lda, int ldb, int ldc,
                        int epi, int rnd)
{
    dim3 block(256);
    dim3 grid(M / BM, N / BN);
    size_t bytes = (size_t)NSTG * (BM * ASTH + BN * ASTH) * 2;
    gemm_f16<<<grid, block, bytes>>>(A, B, bias, C, M, N, K, lda, ldb, ldc, epi, rnd);
}

extern "C" void kernel_launch(void* const* d_in, const int* in_sizes, int n_in,
                              void* d_out, int out_size)
{
    (void)in_sizes; (void)n_in; (void)out_size;
    const int*   idx  = (const int*)  d_in[0];
    const float* wte  = (const float*)d_in[1];
    const float* wpe  = (const float*)d_in[2];
    const float* Wq   = (const float*)d_in[3];
    const float* Wk   = (const float*)d_in[4];
    const float* Wv   = (const float*)d_in[5];
    const float* Wo   = (const float*)d_in[6];
    const float* ln1g = (const float*)d_in[7];
    const float* ln1b = (const float*)d_in[8];
    const float* ln2g = (const float*)d_in[9];
    const float* ln2b = (const float*)d_in[10];
    const float* W1   = (const float*)d_in[11];
    const float* b1   = (const float*)d_in[12];
    const float* W2   = (const float*)d_in[13];
    const float* b2   = (const float*)d_in[14];
    const float* lnfg = (const float*)d_in[15];
    const float* lnfb = (const float*)d_in[16];
    float* out = (float*)d_out;

    float *x, *qkv;
    __half *h, *o, *f, *wqkv, *wo, *w1, *w2, *wt;
    cudaGetSymbolAddress((void**)&x, g_x);
    cudaGetSymbolAddress((void**)&h, g_h);
    cudaGetSymbolAddress((void**)&qkv, g_qkv);
    cudaGetSymbolAddress((void**)&o, g_o);
    cudaGetSymbolAddress((void**)&f, g_f);
    cudaGetSymbolAddress((void**)&wqkv, g_wqkv);
    cudaGetSymbolAddress((void**)&wo, g_wo);
    cudaGetSymbolAddress((void**)&w1, g_w1);
    cudaGetSymbolAddress((void**)&w2, g_w2);
    cudaGetSymbolAddress((void**)&wt, g_wte);

    cudaFuncSetAttribute(gemm_f16, cudaFuncAttributeMaxDynamicSharedMemorySize, 64 * 1024);
    cudaFuncSetAttribute(flash_kernel, cudaFuncAttributeMaxDynamicSharedMemorySize, FA_SMEM);

    // weight prep: transpose + fp16 convert
    {
        dim3 blk(256);
        transpose_qkv<<<dim3(QKVW / 32, EE / 32, LL), blk>>>(Wq, Wk, Wv, wqkv);
        transpose_half<<<dim3(EE / 32, EE / 32, LL), blk>>>(Wo, wo, EE, EE);
        transpose_half<<<dim3(FF / 32, EE / 32, LL), blk>>>(W1, w1, EE, FF);
        transpose_half<<<dim3(EE / 32, FF / 32, LL), blk>>>(W2, w2, FF, EE);
        long long n2 = (long long)VV * EE / 2;
        conv_half<<<(unsigned)((n2 + 255) / 256), blk>>>(wte, wt, n2);
    }

    embed_kernel<<<(MM * EE) / 256, 256>>>(idx, wte, wpe, x);

    for (int l = 0; l < LL; l++) {
        ln_kernel<<<MM, 256>>>(x, ln1g + (long long)l * EE, ln1b + (long long)l * EE, h);

        // fused QKV projection -> fp32 qkv (tf32-rounded for flash)
        gemm(h, wqkv + (long long)l * QKVW * EE, nullptr, qkv,
             MM, QKVW, EE, EE, EE, QKVW, 0, 1);

        // fused causal attention (tf32) -> fp16 o
        {
            dim3 grid(TT / 128, BB * HH);
            flash_kernel<<<grid, 256, FA_SMEM>>>(qkv, o);
        }

        // x += o @ Wo^T
        gemm(o, wo + (long long)l * EE * EE, nullptr, x,
             MM, EE, EE, EE, EE, EE, 3, 0);

        ln_kernel<<<MM, 256>>>(x, ln2g + (long long)l * EE, ln2b + (long long)l * EE, h);

        // f = gelu(h @ W1 + b1) -> fp16
        gemm(h, w1 + (long long)l * FF * EE, b1 + (long long)l * FF, f,
             MM, FF, EE, EE, EE, FF, 1, 0);

        // x += f @ W2 + b2
        gemm(f, w2 + (long long)l * EE * FF, b2 + (long long)l * EE, x,
             MM, EE, FF, FF, FF, EE, 2, 0);
    }

    ln_kernel<<<MM, 256>>>(x, lnfg, lnfb, h);

    // logits = h @ wte^T  (wte already [N][K])
    gemm(h, wt, nullptr, out, MM, VV, EE, EE, EE, VV, 0, 0);
}

// round 13
// speedup vs baseline: 1.6329x; 1.0669x over previous
#include <cuda_runtime.h>
#include <cuda_bf16.h>
#include <cuda_fp16.h>
#include <math.h>
#include <stdint.h>

// Problem constants
#define BB 4
#define TT 1024
#define EE 1024
#define HH 16
#define DD 64
#define FF 4096
#define LL 6
#define VV 32000
#define MM (BB*TT)
#define QKVW 3072
#define LN_EPS 1e-5f

// ---------------------------------------------------------------------------
// Scratch (device globals; no cudaMalloc allowed)
// ---------------------------------------------------------------------------
__device__ float g_x[(size_t)MM * EE];                       // residual (fp32)
__device__ __align__(16) __half g_h[(size_t)MM * EE];        // LN out (fp16)
__device__ __align__(16) __half g_qkv[(size_t)MM * QKVW];    // QKV (fp16)
__device__ __align__(16) __half g_o[(size_t)MM * EE];        // attn out (fp16)
__device__ __align__(16) __half g_f[(size_t)MM * FF];        // FFN mid (fp16)
// fp16 weights, all stored [N][K] (transposed where needed)
__device__ __align__(16) __half g_wqkv[(size_t)LL * QKVW * EE];
__device__ __align__(16) __half g_wo[(size_t)LL * EE * EE];
__device__ __align__(16) __half g_w1[(size_t)LL * FF * EE];
__device__ __align__(16) __half g_w2[(size_t)LL * EE * FF];
__device__ __align__(16) __half g_wte[(size_t)VV * EE];

__device__ __forceinline__ float tf32r(float x) {
    uint32_t u;
    asm("cvt.rna.tf32.f32 %0, %1;" : "=r"(u) : "f"(x));
    return __uint_as_float(u);
}

// Fast exact-grade GELU: A&S 7.1.26 erf, |abs err| <= 1.5e-7
__device__ __forceinline__ float fast_gelu(float v) {
    float x  = v * 0.70710678118654752f;
    float ax = fabsf(x);
    float t  = 1.0f / (1.0f + 0.3275911f * ax);
    float p  = ((((1.061405429f * t - 1.453152027f) * t + 1.421413741f) * t
                 - 0.284496736f) * t + 0.254829592f) * t;
    float er = 1.0f - p * __expf(-x * x);
    er = copysignf(er, x);
    return 0.5f * v * (1.0f + er);
}

// ---------------------------------------------------------------------------
// Weight prep: transpose fp32 [K][N] -> fp16 [N][K]  (per layer z)
// ---------------------------------------------------------------------------
__global__ __launch_bounds__(256) void transpose_half(const float* __restrict__ in,
                                                      __half* __restrict__ out,
                                                      int K, int N)
{
    __shared__ float t[32][33];
    int l = blockIdx.z;
    in  += (size_t)l * K * N;
    out += (size_t)l * K * N;
    int n0 = blockIdx.x * 32, k0 = blockIdx.y * 32;
    int tx = threadIdx.x & 31, ty = threadIdx.x >> 5;   // 32 x 8
    #pragma unroll
    for (int j = 0; j < 4; j++)
        t[ty + 8 * j][tx] = in[(size_t)(k0 + ty + 8 * j) * N + n0 + tx];
    __syncthreads();
    #pragma unroll
    for (int j = 0; j < 4; j++)
        out[(size_t)(n0 + ty + 8 * j) * K + k0 + tx] = __float2half(t[tx][ty + 8 * j]);
}

// Pack+transpose Wq|Wk|Wv [L][E][E] -> [L][3E][E] fp16
__global__ __launch_bounds__(256) void transpose_qkv(const float* __restrict__ Wq,
                                                     const float* __restrict__ Wk,
                                                     const float* __restrict__ Wv,
                                                     __half* __restrict__ out)
{
    __shared__ float t[32][33];
    int l = blockIdx.z;
    int n0 = blockIdx.x * 32, k0 = blockIdx.y * 32;
    int sel = n0 >> 10;
    int nn0 = n0 & 1023;
    const float* src = (sel == 0 ? Wq : sel == 1 ? Wk : Wv) + (size_t)l * EE * EE;
    int tx = threadIdx.x & 31, ty = threadIdx.x >> 5;
    #pragma unroll
    for (int j = 0; j < 4; j++)
        t[ty + 8 * j][tx] = src[(size_t)(k0 + ty + 8 * j) * EE + nn0 + tx];
    __syncthreads();
    #pragma unroll
    for (int j = 0; j < 4; j++)
        out[((size_t)l * QKVW + n0 + ty + 8 * j) * EE + k0 + tx]
            = __float2half(t[tx][ty + 8 * j]);
}

// Elementwise fp32 -> fp16 (wte: already [N][K])
__global__ __launch_bounds__(256) void conv_half(const float* __restrict__ in,
                                                 __half* __restrict__ out, long long n2)
{
    long long i = (long long)blockIdx.x * 256 + threadIdx.x;
    if (i < n2) {
        float2 v = ((const float2*)in)[i];
        ((half2*)out)[i] = __float22half2_rn(v);
    }
}

// ---------------------------------------------------------------------------
// Embedding
// ---------------------------------------------------------------------------
__global__ void embed_kernel(const int* __restrict__ idx,
                             const float* __restrict__ wte,
                             const float* __restrict__ wpe,
                             float* __restrict__ x)
{
    long long i = (long long)blockIdx.x * blockDim.x + threadIdx.x;
    int bt = (int)(i >> 10);
    int e  = (int)(i & 1023);
    int t  = bt & (TT - 1);
    x[i] = wte[(long long)idx[bt] * EE + e] + wpe[(long long)t * EE + e];
}

// ---------------------------------------------------------------------------
// LayerNorm: fp32 in, fp16 out
// ---------------------------------------------------------------------------
__device__ __forceinline__ float warp_sum(float v) {
    #pragma unroll
    for (int o = 16; o > 0; o >>= 1) v += __shfl_xor_sync(0xffffffffu, v, o);
    return v;
}

__global__ __launch_bounds__(256) void ln_kernel(const float* __restrict__ x,
                                                 const float* __restrict__ gamma,
                                                 const float* __restrict__ beta,
                                                 __half* __restrict__ out)
{
    int row = blockIdx.x;
    const float* xr = x + (long long)row * EE;
    __half* orow = out + (long long)row * EE;
    int tid = threadIdx.x;

    float s = 0.f, s2 = 0.f;
    float vals[4];
    #pragma unroll
    for (int u = 0; u < 4; u++) {
        float v = xr[tid + u * 256];
        vals[u] = v;
        s += v; s2 += v * v;
    }
    s  = warp_sum(s);
    s2 = warp_sum(s2);
    __shared__ float shs[8], shs2[8];
    int wid = tid >> 5, lane = tid & 31;
    if (lane == 0) { shs[wid] = s; shs2[wid] = s2; }
    __syncthreads();
    float ts = 0.f, ts2 = 0.f;
    #pragma unroll
    for (int i = 0; i < 8; i++) { ts += shs[i]; ts2 += shs2[i]; }
    float mean = ts * (1.0f / EE);
    float var  = ts2 * (1.0f / EE) - mean * mean;
    float rstd = rsqrtf(var + LN_EPS);
    #pragma unroll
    for (int u = 0; u < 4; u++) {
        int j = tid + u * 256;
        orow[j] = __float2half((vals[u] - mean) * rstd * gamma[j] + beta[j]);
    }
}

// ---------------------------------------------------------------------------
// cp.async / mma / ldmatrix helpers
// ---------------------------------------------------------------------------
__device__ __forceinline__ void cpa16(uint32_t dst, const void* src) {
    asm volatile("cp.async.cg.shared.global [%0], [%1], 16;" :: "r"(dst), "l"(src));
}
__device__ __forceinline__ void cpa_commit() {
    asm volatile("cp.async.commit_group;");
}
template<int N>
__device__ __forceinline__ void cpa_wait() {
    asm volatile("cp.async.wait_group %0;" :: "n"(N));
}

__device__ __forceinline__ void mma_f16(float* c, const uint32_t* a, const uint32_t* b) {
    asm volatile(
        "mma.sync.aligned.m16n8k16.row.col.f32.f16.f16.f32 "
        "{%0,%1,%2,%3}, {%4,%5,%6,%7}, {%8,%9}, {%0,%1,%2,%3};\n"
        : "+f"(c[0]), "+f"(c[1]), "+f"(c[2]), "+f"(c[3])
        : "r"(a[0]), "r"(a[1]), "r"(a[2]), "r"(a[3]), "r"(b[0]), "r"(b[1]));
}

// B-operand gather from k-major fp16 smem (two 8x8 b16 tiles, transposed)
__device__ __forceinline__ void ldmx2t(uint32_t& r0, uint32_t& r1, uint32_t saddr) {
    asm volatile("ldmatrix.sync.aligned.m8n8.x2.trans.shared.b16 {%0,%1}, [%2];"
                 : "=r"(r0), "=r"(r1) : "r"(saddr));
}

// ---------------------------------------------------------------------------
// Fused flash attention (causal), fp16 tensor cores, fp32 accum/softmax.
// CTA: 128 q-rows of one (b,h). 8 warps x 16 rows. D=64.
// smem (halves): [K0(128x72) V0(128x72) | K1 V1 | QP(128x136)]
// ---------------------------------------------------------------------------
#define KSTH 72
#define VSTH 72
#define QSTH 136
#define KVSTGH (128*KSTH + 128*VSTH)      // 18432 halves
#define PS_OFFH (2*KVSTGH)                // 36864
#define FA_SMEM ((PS_OFFH + 128*QSTH) * 2)  // 108544 bytes

__global__ __launch_bounds__(256, 1) void flash_kernel(
    const __half* __restrict__ QKV, __half* __restrict__ O)
{
    extern __shared__ __half smh[];

    int mb = gridDim.x - 1 - blockIdx.x;   // heavy blocks first
    int bh = blockIdx.y;
    int b = bh >> 4, h = bh & 15;
    int m0 = mb * 128;

    const __half* Qp = QKV + (long long)b * TT * QKVW + (long long)h * DD;
    const __half* Kp = Qp + EE;
    const __half* Vp = Qp + 2 * EE;
    __half*       Op = O + (long long)b * TT * EE + (long long)h * DD;

    int tid = threadIdx.x, warp = tid >> 5, lane = tid & 31;
    int g = lane >> 2, tg = lane & 3;

    uint32_t smem_u32 = (uint32_t)__cvta_generic_to_shared(smh);

    auto load_kv = [&](int stage, int j0) {
        uint32_t base = smem_u32 + (uint32_t)(stage * KVSTGH) * 2u;
        #pragma unroll
        for (int i = 0; i < 4; i++) {
            int idx = tid + i * 256;
            int row = idx >> 3;
            int c8  = (idx & 7) << 3;
            cpa16(base + (uint32_t)(row * KSTH + c8) * 2u,
                  Kp + (long long)(j0 + row) * QKVW + c8);
        }
        #pragma unroll
        for (int i = 0; i < 4; i++) {
            int idx = tid + i * 256;
            int row = idx >> 3;
            int c8  = (idx & 7) << 3;
            cpa16(base + (uint32_t)(128 * KSTH + row * VSTH + c8) * 2u,
                  Vp + (long long)(j0 + row) * QKVW + c8);
        }
    };

    // stage Q into QP region, load KV block 0
    {
        uint32_t qbase = smem_u32 + (uint32_t)PS_OFFH * 2u;
        #pragma unroll
        for (int i = 0; i < 4; i++) {
            int idx = tid + i * 256;
            int row = idx >> 3;
            int c8  = (idx & 7) << 3;
            cpa16(qbase + (uint32_t)(row * QSTH + c8) * 2u,
                  Qp + (long long)(m0 + row) * QKVW + c8);
        }
        cpa_commit();
        load_kv(0, 0);
        cpa_commit();
        cpa_wait<0>();
        __syncthreads();
    }

    // Q fragments: 4 k-chunks of 16
    uint32_t qf[4][4];
    {
        const __half* Qs = smh + PS_OFFH;
        #pragma unroll
        for (int kc = 0; kc < 4; kc++) {
            const __half* ap = Qs + (warp * 16 + g) * QSTH + kc * 16 + 2 * tg;
            qf[kc][0] = *(const uint32_t*)(ap);
            qf[kc][1] = *(const uint32_t*)(ap + 8 * QSTH);
            qf[kc][2] = *(const uint32_t*)(ap + 8);
            qf[kc][3] = *(const uint32_t*)(ap + 8 * QSTH + 8);
        }
    }
    __syncthreads();  // QP region now free for P tiles

    float m_[2] = {-1e30f, -1e30f};
    float l_[2] = {0.f, 0.f};
    float oacc[8][4];
    #pragma unroll
    for (int i = 0; i < 8; i++)
        #pragma unroll
        for (int c = 0; c < 4; c++) oacc[i][c] = 0.f;

    int nblk = mb;
    for (int jb = 0; jb <= nblk; jb++) {
        cpa_wait<0>();
        __syncthreads();
        if (jb < nblk) {
            load_kv((jb + 1) & 1, (jb + 1) * 128);
            cpa_commit();
        }

        const __half* Ks = smh + (jb & 1) * KVSTGH;
        uint32_t vs_u32 = smem_u32 + (uint32_t)((jb & 1) * KVSTGH + 128 * KSTH) * 2u;

        // ---- S = Q @ K^T : warp computes 16 x 128 ----
        float sacc[16][4];
        #pragma unroll
        for (int nf = 0; nf < 16; nf++)
            #pragma unroll
            for (int c = 0; c < 4; c++) sacc[nf][c] = 0.f;

        #pragma unroll
        for (int kc = 0; kc < 4; kc++) {
            #pragma unroll
            for (int nf = 0; nf < 16; nf++) {
                const __half* bp = Ks + (nf * 8 + g) * KSTH + kc * 16 + 2 * tg;
                uint32_t bfr[2];
                bfr[0] = *(const uint32_t*)(bp);
                bfr[1] = *(const uint32_t*)(bp + 8);
                mma_f16(sacc[nf], qf[kc], bfr);
            }
        }

        // scale by 1/sqrt(D)
        #pragma unroll
        for (int nf = 0; nf < 16; nf++)
            #pragma unroll
            for (int c = 0; c < 4; c++) sacc[nf][c] *= 0.125f;

        // ---- causal mask on diagonal block ----
        if (jb == nblk) {
            int i0 = m0 + warp * 16 + g;
            #pragma unroll
            for (int nf = 0; nf < 16; nf++) {
                int j0c = jb * 128 + nf * 8 + 2 * tg;
                if (j0c     > i0)     sacc[nf][0] = -1e30f;
                if (j0c + 1 > i0)     sacc[nf][1] = -1e30f;
                if (j0c     > i0 + 8) sacc[nf][2] = -1e30f;
                if (j0c + 1 > i0 + 8) sacc[nf][3] = -1e30f;
            }
        }

        // ---- online softmax (fp32) ----
        float rm0 = -1e30f, rm1 = -1e30f;
        #pragma unroll
        for (int nf = 0; nf < 16; nf++) {
            rm0 = fmaxf(rm0, fmaxf(sacc[nf][0], sacc[nf][1]));
            rm1 = fmaxf(rm1, fmaxf(sacc[nf][2], sacc[nf][3]));
        }
        rm0 = fmaxf(rm0, __shfl_xor_sync(0xffffffffu, rm0, 1));
        rm0 = fmaxf(rm0, __shfl_xor_sync(0xffffffffu, rm0, 2));
        rm1 = fmaxf(rm1, __shfl_xor_sync(0xffffffffu, rm1, 1));
        rm1 = fmaxf(rm1, __shfl_xor_sync(0xffffffffu, rm1, 2));

        float mn0 = fmaxf(m_[0], rm0), mn1 = fmaxf(m_[1], rm1);
        float sc0 = __expf(m_[0] - mn0), sc1 = __expf(m_[1] - mn1);
        m_[0] = mn0; m_[1] = mn1;

        float rs0 = 0.f, rs1 = 0.f;
        #pragma unroll
        for (int nf = 0; nf < 16; nf++) {
            sacc[nf][0] = __expf(sacc[nf][0] - mn0);
            sacc[nf][1] = __expf(sacc[nf][1] - mn0);
            sacc[nf][2] = __expf(sacc[nf][2] - mn1);
            sacc[nf][3] = __expf(sacc[nf][3] - mn1);
            rs0 += sacc[nf][0] + sacc[nf][1];
            rs1 += sacc[nf][2] + sacc[nf][3];
        }
        rs0 += __shfl_xor_sync(0xffffffffu, rs0, 1);
        rs0 += __shfl_xor_sync(0xffffffffu, rs0, 2);
        rs1 += __shfl_xor_sync(0xffffffffu, rs1, 1);
        rs1 += __shfl_xor_sync(0xffffffffu, rs1, 2);
        l_[0] = l_[0] * sc0 + rs0;
        l_[1] = l_[1] * sc1 + rs1;

        #pragma unroll
        for (int nf = 0; nf < 8; nf++) {
            oacc[nf][0] *= sc0; oacc[nf][1] *= sc0;
            oacc[nf][2] *= sc1; oacc[nf][3] *= sc1;
        }

        // ---- P -> smem (fp16, own 16-row band only) ----
        {
            __half* Pw = smh + PS_OFFH + (warp * 16 + g) * QSTH;
            #pragma unroll
            for (int nf = 0; nf < 16; nf++) {
                int c = nf * 8 + 2 * tg;
                *(half2*)(Pw + c) =
                    __float22half2_rn(make_float2(sacc[nf][0], sacc[nf][1]));
                *(half2*)(Pw + 8 * QSTH + c) =
                    __float22half2_rn(make_float2(sacc[nf][2], sacc[nf][3]));
            }
        }
        __syncwarp();

        // ---- O += P @ V : 16 x 64, k = 128, V frags via ldmatrix.trans ----
        const __half* Pr = smh + PS_OFFH + (warp * 16 + g) * QSTH;
        #pragma unroll
        for (int kc = 0; kc < 8; kc++) {
            uint32_t afr[4];
            const __half* ap = Pr + kc * 16 + 2 * tg;
            afr[0] = *(const uint32_t*)(ap);
            afr[1] = *(const uint32_t*)(ap + 8 * QSTH);
            afr[2] = *(const uint32_t*)(ap + 8);
            afr[3] = *(const uint32_t*)(ap + 8 * QSTH + 8);
            int vrow = kc * 16 + (lane & 15);
            #pragma unroll
            for (int nf = 0; nf < 8; nf++) {
                uint32_t saddr = vs_u32 + (uint32_t)(vrow * VSTH + nf * 8) * 2u;
                uint32_t bfr0, bfr1;
                ldmx2t(bfr0, bfr1, saddr);
                uint32_t bfr[2] = {bfr0, bfr1};
                mma_f16(oacc[nf], afr, bfr);
            }
        }
    }

    float inv0 = 1.0f / l_[0], inv1 = 1.0f / l_[1];
    int r0 = m0 + warp * 16 + g;
    #pragma unroll
    for (int nf = 0; nf < 8; nf++) {
        int c = nf * 8 + 2 * tg;
        __half* o0 = Op + (long long)r0 * EE + c;
        __half* o1 = Op + (long long)(r0 + 8) * EE + c;
        *(half2*)o0 = __float22half2_rn(make_float2(oacc[nf][0] * inv0, oacc[nf][1] * inv0));
        *(half2*)o1 = __float22half2_rn(make_float2(oacc[nf][2] * inv1, oacc[nf][3] * inv1));
    }
}

// ---------------------------------------------------------------------------
// fp16 tensor-core GEMM (validated R11): C = epi( A[M,K]h @ B[N,K]h^T ),
// fp32 accumulate. BM=128, BN=128, BK=32, 3-stage cp.async, warp tile 64x32.
// epi: 0=store f32  1=gelu(acc+bias)->half  2=C+=acc+bias (f32)
//      3=C+=acc (f32)  4=store half
// ---------------------------------------------------------------------------
#define BM 128
#define BN 128
#define BK 32
#define ASTH 40
#define NSTG 3

__global__ __launch_bounds__(256, 2) void gemm_f16(
    const __half* __restrict__ A, const __half* __restrict__ Bm,
    const float* __restrict__ bias, void* __restrict__ Cv,
    int M, int N, int K, int lda, int ldb, int ldc,
    int epi, int rnd)
{
    constexpr int ASZ = BM * ASTH;
    constexpr int BSZ = BN * ASTH;
    constexpr int ST  = ASZ + BSZ;

    extern __shared__ __half smh[];

    int m0 = blockIdx.x * BM;
    int n0 = blockIdx.y * BN;
    int nt = K / BK;

    int tid  = threadIdx.x;
    int warp = tid >> 5, lane = tid & 31;
    int g  = lane >> 2;
    int tg = lane & 3;
    int warp_m = warp >> 2;
    int warp_n = warp & 3;

    uint32_t smem_u32 = (uint32_t)__cvta_generic_to_shared(smh);

    auto load_tiles = [&](int st, int k0) {
        uint32_t sb = smem_u32 + (uint32_t)(st * ST) * 2u;
        #pragma unroll
        for (int i = 0; i < 2; i++) {
            int idx = tid + i * 256;
            int row = idx >> 2;
            int kc  = (idx & 3) << 3;
            cpa16(sb + (uint32_t)(row * ASTH + kc) * 2u,
                  A + (long long)(m0 + row) * lda + k0 + kc);
        }
        #pragma unroll
        for (int i = 0; i < 2; i++) {
            int idx = tid + i * 256;
            int row = idx >> 2;
            int kc  = (idx & 3) << 3;
            cpa16(sb + (uint32_t)(ASZ + row * ASTH + kc) * 2u,
                  Bm + (long long)(n0 + row) * ldb + k0 + kc);
        }
    };

    float acc[4][4][4];
    #pragma unroll
    for (int i = 0; i < 4; i++)
        #pragma unroll
        for (int j = 0; j < 4; j++)
            #pragma unroll
            for (int c = 0; c < 4; c++) acc[i][j][c] = 0.f;

    load_tiles(0, 0);
    cpa_commit();
    if (nt > 1) load_tiles(1, BK);
    cpa_commit();

    int cs = 0, ps = 2;
    for (int it = 0; it < nt; it++) {
        cpa_wait<1>();
        __syncthreads();
        if (it + 2 < nt) load_tiles(ps, (it + 2) * BK);
        cpa_commit();

        const __half* Ab = smh + cs * ST;
        const __half* Bb = Ab + ASZ;

        #pragma unroll
        for (int ks = 0; ks < BK; ks += 16) {
            uint32_t afr[4][4];
            #pragma unroll
            for (int mi = 0; mi < 4; mi++) {
                const __half* ap = Ab + (warp_m * 64 + mi * 16 + g) * ASTH + ks + 2 * tg;
                afr[mi][0] = *(const uint32_t*)(ap);
                afr[mi][1] = *(const uint32_t*)(ap + 8 * ASTH);
                afr[mi][2] = *(const uint32_t*)(ap + 8);
                afr[mi][3] = *(const uint32_t*)(ap + 8 * ASTH + 8);
            }
            #pragma unroll
            for (int ni = 0; ni < 4; ni++) {
                const __half* bp = Bb + (warp_n * 32 + ni * 8 + g) * ASTH + ks + 2 * tg;
                uint32_t bfr[2];
                bfr[0] = *(const uint32_t*)(bp);
                bfr[1] = *(const uint32_t*)(bp + 8);
                #pragma unroll
                for (int mi = 0; mi < 4; mi++)
                    mma_f16(acc[mi][ni], afr[mi], bfr);
            }
        }

        cs++; if (cs == NSTG) cs = 0;
        ps++; if (ps == NSTG) ps = 0;
    }

    #pragma unroll
    for (int mi = 0; mi < 4; mi++) {
        #pragma unroll
        for (int ni = 0; ni < 4; ni++) {
            int r0 = m0 + warp_m * 64 + mi * 16 + g;
            int c0 = n0 + warp_n * 32 + ni * 8 + 2 * tg;
            #pragma unroll
            for (int p = 0; p < 2; p++) {
                int m = r0 + p * 8;
                float vx = acc[mi][ni][2 * p];
                float vy = acc[mi][ni][2 * p + 1];
                if (epi == 1) {
                    vx = fast_gelu(vx + bias[c0]);
                    vy = fast_gelu(vy + bias[c0 + 1]);
                    __half* cp = (__half*)Cv + (long long)m * ldc + c0;
                    *(half2*)cp = __float22half2_rn(make_float2(vx, vy));
                } else if (epi == 4) {
                    __half* cp = (__half*)Cv + (long long)m * ldc + c0;
                    *(half2*)cp = __float22half2_rn(make_float2(vx, vy));
                } else {
                    float* cp = (float*)Cv + (long long)m * ldc + c0;
                    if (epi == 2) {
                        float2 old = *(const float2*)cp;
                        vx += bias[c0]     + old.x;
                        vy += bias[c0 + 1] + old.y;
                    } else if (epi == 3) {
                        float2 old = *(const float2*)cp;
                        vx += old.x;
                        vy += old.y;
                    }
                    if (rnd) { vx = tf32r(vx); vy = tf32r(vy); }
                    *(float2*)cp = make_float2(vx, vy);
                }
            }
        }
    }
}

// ---------------------------------------------------------------------------
// Host-side launch helper
// ---------------------------------------------------------------------------
static inline void gemm(const __half* A, const __half* B, const float* bias, void* C,
                        int M, int N, int K, int lda, int ldb, int ldc,
                        int epi, int rnd)
{
    dim3 block(256);
    dim3 grid(M / BM, N / BN);
    size_t bytes = (size_t)NSTG * (BM * ASTH + BN * ASTH) * 2;
    gemm_f16<<<grid, block, bytes>>>(A, B, bias, C, M, N, K, lda, ldb, ldc, epi, rnd);
}

extern "C" void kernel_launch(void* const* d_in, const int* in_sizes, int n_in,
                              void* d_out, int out_size)
{
    (void)in_sizes; (void)n_in; (void)out_size;
    const int*   idx  = (const int*)  d_in[0];
    const float* wte  = (const float*)d_in[1];
    const float* wpe  = (const float*)d_in[2];
    const float* Wq   = (const float*)d_in[3];
    const float* Wk   = (const float*)d_in[4];
    const float* Wv   = (const float*)d_in[5];
    const float* Wo   = (const float*)d_in[6];
    const float* ln1g = (const float*)d_in[7];
    const float* ln1b = (const float*)d_in[8];
    const float* ln2g = (const float*)d_in[9];
    const float* ln2b = (const float*)d_in[10];
    const float* W1   = (const float*)d_in[11];
    const float* b1   = (const float*)d_in[12];
    const float* W2   = (const float*)d_in[13];
    const float* b2   = (const float*)d_in[14];
    const float* lnfg = (const float*)d_in[15];
    const float* lnfb = (const float*)d_in[16];
    float* out = (float*)d_out;

    float *x;
    __half *h, *qkv, *o, *f, *wqkv, *wo, *w1, *w2, *wt;
    cudaGetSymbolAddress((void**)&x, g_x);
    cudaGetSymbolAddress((void**)&h, g_h);
    cudaGetSymbolAddress((void**)&qkv, g_qkv);
    cudaGetSymbolAddress((void**)&o, g_o);
    cudaGetSymbolAddress((void**)&f, g_f);
    cudaGetSymbolAddress((void**)&wqkv, g_wqkv);
    cudaGetSymbolAddress((void**)&wo, g_wo);
    cudaGetSymbolAddress((void**)&w1, g_w1);
    cudaGetSymbolAddress((void**)&w2, g_w2);
    cudaGetSymbolAddress((void**)&wt, g_wte);

    cudaFuncSetAttribute(gemm_f16, cudaFuncAttributeMaxDynamicSharedMemorySize, 64 * 1024);
    cudaFuncSetAttribute(flash_kernel, cudaFuncAttributeMaxDynamicSharedMemorySize, FA_SMEM);

    // weight prep: transpose + fp16 convert
    {
        dim3 blk(256);
        transpose_qkv<<<dim3(QKVW / 32, EE / 32, LL), blk>>>(Wq, Wk, Wv, wqkv);
        transpose_half<<<dim3(EE / 32, EE / 32, LL), blk>>>(Wo, wo, EE, EE);
        transpose_half<<<dim3(FF / 32, EE / 32, LL), blk>>>(W1, w1, EE, FF);
        transpose_half<<<dim3(EE / 32, FF / 32, LL), blk>>>(W2, w2, FF, EE);
        long long n2 = (long long)VV * EE / 2;
        conv_half<<<(unsigned)((n2 + 255) / 256), blk>>>(wte, wt, n2);
    }

    embed_kernel<<<(MM * EE) / 256, 256>>>(idx, wte, wpe, x);

    for (int l = 0; l < LL; l++) {
        ln_kernel<<<MM, 256>>>(x, ln1g + (long long)l * EE, ln1b + (long long)l * EE, h);

        // fused QKV projection -> fp16 qkv
        gemm(h, wqkv + (long long)l * QKVW * EE, nullptr, qkv,
             MM, QKVW, EE, EE, EE, QKVW, 4, 0);

        // fused causal attention (fp16) -> fp16 o
        {
            dim3 grid(TT / 128, BB * HH);
            flash_kernel<<<grid, 256, FA_SMEM>>>(qkv, o);
        }

        // x += o @ Wo^T
        gemm(o, wo + (long long)l * EE * EE, nullptr, x,
             MM, EE, EE, EE, EE, EE, 3, 0);

        ln_kernel<<<MM, 256>>>(x, ln2g + (long long)l * EE, ln2b + (long long)l * EE, h);

        // f = gelu(h @ W1 + b1) -> fp16
        gemm(h, w1 + (long long)l * FF * EE, b1 + (long long)l * FF, f,
             MM, FF, EE, EE, EE, FF, 1, 0);

        // x += f @ W2 + b2
        gemm(f, w2 + (long long)l * EE * FF, b2 + (long long)l * EE, x,
             MM, EE, FF, FF, FF, EE, 2, 0);
    }

    ln_kernel<<<MM, 256>>>(x, lnfg, lnfb, h);

    // logits = h @ wte^T
    gemm(h, wt, nullptr, out, MM, VV, EE, EE, EE, VV, 0, 0);
}

// round 14
// speedup vs baseline: 1.6374x; 1.0027x over previous
#include <cuda_runtime.h>
#include <cuda_bf16.h>
#include <cuda_fp16.h>
#include <math.h>
#include <stdint.h>

// Problem constants
#define BB 4
#define TT 1024
#define EE 1024
#define HH 16
#define DD 64
#define FF 4096
#define LL 6
#define VV 32000
#define MM (BB*TT)
#define QKVW 3072
#define LN_EPS 1e-5f

// ---------------------------------------------------------------------------
// Scratch (device globals; no cudaMalloc allowed)
// ---------------------------------------------------------------------------
__device__ float g_x[(size_t)MM * EE];                       // residual (fp32)
__device__ __align__(16) __half g_h[(size_t)MM * EE];        // LN out (fp16)
__device__ __align__(16) __half g_qkv[(size_t)MM * QKVW];    // QKV (fp16)
__device__ __align__(16) __half g_o[(size_t)MM * EE];        // attn out (fp16)
__device__ __align__(16) __half g_f[(size_t)MM * FF];        // FFN mid (fp16)
// fp16 weights, all stored [N][K] (transposed where needed)
__device__ __align__(16) __half g_wqkv[(size_t)LL * QKVW * EE];
__device__ __align__(16) __half g_wo[(size_t)LL * EE * EE];
__device__ __align__(16) __half g_w1[(size_t)LL * FF * EE];
__device__ __align__(16) __half g_w2[(size_t)LL * EE * FF];
__device__ __align__(16) __half g_wte[(size_t)VV * EE];

__device__ __forceinline__ float tf32r(float x) {
    uint32_t u;
    asm("cvt.rna.tf32.f32 %0, %1;" : "=r"(u) : "f"(x));
    return __uint_as_float(u);
}

// Fast exact-grade GELU: A&S 7.1.26 erf, |abs err| <= 1.5e-7
__device__ __forceinline__ float fast_gelu(float v) {
    float x  = v * 0.70710678118654752f;
    float ax = fabsf(x);
    float t  = 1.0f / (1.0f + 0.3275911f * ax);
    float p  = ((((1.061405429f * t - 1.453152027f) * t + 1.421413741f) * t
                 - 0.284496736f) * t + 0.254829592f) * t;
    float er = 1.0f - p * __expf(-x * x);
    er = copysignf(er, x);
    return 0.5f * v * (1.0f + er);
}

// ---------------------------------------------------------------------------
// Weight prep: transpose fp32 [K][N] -> fp16 [N][K]  (per layer z)
// ---------------------------------------------------------------------------
__global__ __launch_bounds__(256) void transpose_half(const float* __restrict__ in,
                                                      __half* __restrict__ out,
                                                      int K, int N)
{
    __shared__ float t[32][33];
    int l = blockIdx.z;
    in  += (size_t)l * K * N;
    out += (size_t)l * K * N;
    int n0 = blockIdx.x * 32, k0 = blockIdx.y * 32;
    int tx = threadIdx.x & 31, ty = threadIdx.x >> 5;   // 32 x 8
    #pragma unroll
    for (int j = 0; j < 4; j++)
        t[ty + 8 * j][tx] = in[(size_t)(k0 + ty + 8 * j) * N + n0 + tx];
    __syncthreads();
    #pragma unroll
    for (int j = 0; j < 4; j++)
        out[(size_t)(n0 + ty + 8 * j) * K + k0 + tx] = __float2half(t[tx][ty + 8 * j]);
}

// Pack+transpose Wq|Wk|Wv [L][E][E] -> [L][3E][E] fp16
__global__ __launch_bounds__(256) void transpose_qkv(const float* __restrict__ Wq,
                                                     const float* __restrict__ Wk,
                                                     const float* __restrict__ Wv,
                                                     __half* __restrict__ out)
{
    __shared__ float t[32][33];
    int l = blockIdx.z;
    int n0 = blockIdx.x * 32, k0 = blockIdx.y * 32;
    int sel = n0 >> 10;
    int nn0 = n0 & 1023;
    const float* src = (sel == 0 ? Wq : sel == 1 ? Wk : Wv) + (size_t)l * EE * EE;
    int tx = threadIdx.x & 31, ty = threadIdx.x >> 5;
    #pragma unroll
    for (int j = 0; j < 4; j++)
        t[ty + 8 * j][tx] = src[(size_t)(k0 + ty + 8 * j) * EE + nn0 + tx];
    __syncthreads();
    #pragma unroll
    for (int j = 0; j < 4; j++)
        out[((size_t)l * QKVW + n0 + ty + 8 * j) * EE + k0 + tx]
            = __float2half(t[tx][ty + 8 * j]);
}

// Elementwise fp32 -> fp16 (wte: already [N][K])
__global__ __launch_bounds__(256) void conv_half(const float* __restrict__ in,
                                                 __half* __restrict__ out, long long n2)
{
    long long i = (long long)blockIdx.x * 256 + threadIdx.x;
    if (i < n2) {
        float2 v = ((const float2*)in)[i];
        ((half2*)out)[i] = __float22half2_rn(v);
    }
}

// ---------------------------------------------------------------------------
// Embedding
// ---------------------------------------------------------------------------
__global__ void embed_kernel(const int* __restrict__ idx,
                             const float* __restrict__ wte,
                             const float* __restrict__ wpe,
                             float* __restrict__ x)
{
    long long i = (long long)blockIdx.x * blockDim.x + threadIdx.x;
    int bt = (int)(i >> 10);
    int e  = (int)(i & 1023);
    int t  = bt & (TT - 1);
    x[i] = wte[(long long)idx[bt] * EE + e] + wpe[(long long)t * EE + e];
}

// ---------------------------------------------------------------------------
// LayerNorm: fp32 in, fp16 out
// ---------------------------------------------------------------------------
__device__ __forceinline__ float warp_sum(float v) {
    #pragma unroll
    for (int o = 16; o > 0; o >>= 1) v += __shfl_xor_sync(0xffffffffu, v, o);
    return v;
}

__global__ __launch_bounds__(256) void ln_kernel(const float* __restrict__ x,
                                                 const float* __restrict__ gamma,
                                                 const float* __restrict__ beta,
                                                 __half* __restrict__ out)
{
    int row = blockIdx.x;
    const float* xr = x + (long long)row * EE;
    __half* orow = out + (long long)row * EE;
    int tid = threadIdx.x;

    float s = 0.f, s2 = 0.f;
    float vals[4];
    #pragma unroll
    for (int u = 0; u < 4; u++) {
        float v = xr[tid + u * 256];
        vals[u] = v;
        s += v; s2 += v * v;
    }
    s  = warp_sum(s);
    s2 = warp_sum(s2);
    __shared__ float shs[8], shs2[8];
    int wid = tid >> 5, lane = tid & 31;
    if (lane == 0) { shs[wid] = s; shs2[wid] = s2; }
    __syncthreads();
    float ts = 0.f, ts2 = 0.f;
    #pragma unroll
    for (int i = 0; i < 8; i++) { ts += shs[i]; ts2 += shs2[i]; }
    float mean = ts * (1.0f / EE);
    float var  = ts2 * (1.0f / EE) - mean * mean;
    float rstd = rsqrtf(var + LN_EPS);
    #pragma unroll
    for (int u = 0; u < 4; u++) {
        int j = tid + u * 256;
        orow[j] = __float2half((vals[u] - mean) * rstd * gamma[j] + beta[j]);
    }
}

// ---------------------------------------------------------------------------
// cp.async / mma / ldmatrix helpers
// ---------------------------------------------------------------------------
__device__ __forceinline__ void cpa16(uint32_t dst, const void* src) {
    asm volatile("cp.async.cg.shared.global [%0], [%1], 16;" :: "r"(dst), "l"(src));
}
__device__ __forceinline__ void cpa_commit() {
    asm volatile("cp.async.commit_group;");
}
template<int N>
__device__ __forceinline__ void cpa_wait() {
    asm volatile("cp.async.wait_group %0;" :: "n"(N));
}

__device__ __forceinline__ void mma_f16(float* c, const uint32_t* a, const uint32_t* b) {
    asm volatile(
        "mma.sync.aligned.m16n8k16.row.col.f32.f16.f16.f32 "
        "{%0,%1,%2,%3}, {%4,%5,%6,%7}, {%8,%9}, {%0,%1,%2,%3};\n"
        : "+f"(c[0]), "+f"(c[1]), "+f"(c[2]), "+f"(c[3])
        : "r"(a[0]), "r"(a[1]), "r"(a[2]), "r"(a[3]), "r"(b[0]), "r"(b[1]));
}

// B-operand gather from k-major fp16 smem (two 8x8 b16 tiles, transposed)
__device__ __forceinline__ void ldmx2t(uint32_t& r0, uint32_t& r1, uint32_t saddr) {
    asm volatile("ldmatrix.sync.aligned.m8n8.x2.trans.shared.b16 {%0,%1}, [%2];"
                 : "=r"(r0), "=r"(r1) : "r"(saddr));
}

// ---------------------------------------------------------------------------
// Fused flash attention (causal), fp16 tensor cores, fp32 accum/softmax.
// CTA: 128 q-rows of one (b,h). 8 warps x 16 rows. D=64.
// smem (halves): [K0(128x72) V0(128x72) | K1 V1 | QP(128x136)]
// ---------------------------------------------------------------------------
#define KSTH 72
#define VSTH 72
#define QSTH 136
#define KVSTGH (128*KSTH + 128*VSTH)      // 18432 halves
#define PS_OFFH (2*KVSTGH)                // 36864
#define FA_SMEM ((PS_OFFH + 128*QSTH) * 2)  // 108544 bytes

__global__ __launch_bounds__(256, 1) void flash_kernel(
    const __half* __restrict__ QKV, __half* __restrict__ O)
{
    extern __shared__ __half smh[];

    int mb = gridDim.x - 1 - blockIdx.x;   // heavy blocks first
    int bh = blockIdx.y;
    int b = bh >> 4, h = bh & 15;
    int m0 = mb * 128;

    const __half* Qp = QKV + (long long)b * TT * QKVW + (long long)h * DD;
    const __half* Kp = Qp + EE;
    const __half* Vp = Qp + 2 * EE;
    __half*       Op = O + (long long)b * TT * EE + (long long)h * DD;

    int tid = threadIdx.x, warp = tid >> 5, lane = tid & 31;
    int g = lane >> 2, tg = lane & 3;

    uint32_t smem_u32 = (uint32_t)__cvta_generic_to_shared(smh);

    auto load_kv = [&](int stage, int j0) {
        uint32_t base = smem_u32 + (uint32_t)(stage * KVSTGH) * 2u;
        #pragma unroll
        for (int i = 0; i < 4; i++) {
            int idx = tid + i * 256;
            int row = idx >> 3;
            int c8  = (idx & 7) << 3;
            cpa16(base + (uint32_t)(row * KSTH + c8) * 2u,
                  Kp + (long long)(j0 + row) * QKVW + c8);
        }
        #pragma unroll
        for (int i = 0; i < 4; i++) {
            int idx = tid + i * 256;
            int row = idx >> 3;
            int c8  = (idx & 7) << 3;
            cpa16(base + (uint32_t)(128 * KSTH + row * VSTH + c8) * 2u,
                  Vp + (long long)(j0 + row) * QKVW + c8);
        }
    };

    // stage Q into QP region, load KV block 0
    {
        uint32_t qbase = smem_u32 + (uint32_t)PS_OFFH * 2u;
        #pragma unroll
        for (int i = 0; i < 4; i++) {
            int idx = tid + i * 256;
            int row = idx >> 3;
            int c8  = (idx & 7) << 3;
            cpa16(qbase + (uint32_t)(row * QSTH + c8) * 2u,
                  Qp + (long long)(m0 + row) * QKVW + c8);
        }
        cpa_commit();
        load_kv(0, 0);
        cpa_commit();
        cpa_wait<0>();
        __syncthreads();
    }

    // Q fragments: 4 k-chunks of 16
    uint32_t qf[4][4];
    {
        const __half* Qs = smh + PS_OFFH;
        #pragma unroll
        for (int kc = 0; kc < 4; kc++) {
            const __half* ap = Qs + (warp * 16 + g) * QSTH + kc * 16 + 2 * tg;
            qf[kc][0] = *(const uint32_t*)(ap);
            qf[kc][1] = *(const uint32_t*)(ap + 8 * QSTH);
            qf[kc][2] = *(const uint32_t*)(ap + 8);
            qf[kc][3] = *(const uint32_t*)(ap + 8 * QSTH + 8);
        }
    }
    __syncthreads();  // QP region now free for P tiles

    float m_[2] = {-1e30f, -1e30f};
    float l_[2] = {0.f, 0.f};
    float oacc[8][4];
    #pragma unroll
    for (int i = 0; i < 8; i++)
        #pragma unroll
        for (int c = 0; c < 4; c++) oacc[i][c] = 0.f;

    int nblk = mb;
    for (int jb = 0; jb <= nblk; jb++) {
        cpa_wait<0>();
        __syncthreads();
        if (jb < nblk) {
            load_kv((jb + 1) & 1, (jb + 1) * 128);
            cpa_commit();
        }

        const __half* Ks = smh + (jb & 1) * KVSTGH;
        uint32_t vs_u32 = smem_u32 + (uint32_t)((jb & 1) * KVSTGH + 128 * KSTH) * 2u;

        // ---- S = Q @ K^T : warp computes 16 x 128 ----
        float sacc[16][4];
        #pragma unroll
        for (int nf = 0; nf < 16; nf++)
            #pragma unroll
            for (int c = 0; c < 4; c++) sacc[nf][c] = 0.f;

        #pragma unroll
        for (int kc = 0; kc < 4; kc++) {
            #pragma unroll
            for (int nf = 0; nf < 16; nf++) {
                const __half* bp = Ks + (nf * 8 + g) * KSTH + kc * 16 + 2 * tg;
                uint32_t bfr[2];
                bfr[0] = *(const uint32_t*)(bp);
                bfr[1] = *(const uint32_t*)(bp + 8);
                mma_f16(sacc[nf], qf[kc], bfr);
            }
        }

        // scale by 1/sqrt(D)
        #pragma unroll
        for (int nf = 0; nf < 16; nf++)
            #pragma unroll
            for (int c = 0; c < 4; c++) sacc[nf][c] *= 0.125f;

        // ---- causal mask on diagonal block ----
        if (jb == nblk) {
            int i0 = m0 + warp * 16 + g;
            #pragma unroll
            for (int nf = 0; nf < 16; nf++) {
                int j0c = jb * 128 + nf * 8 + 2 * tg;
                if (j0c     > i0)     sacc[nf][0] = -1e30f;
                if (j0c + 1 > i0)     sacc[nf][1] = -1e30f;
                if (j0c     > i0 + 8) sacc[nf][2] = -1e30f;
                if (j0c + 1 > i0 + 8) sacc[nf][3] = -1e30f;
            }
        }

        // ---- online softmax (fp32) ----
        float rm0 = -1e30f, rm1 = -1e30f;
        #pragma unroll
        for (int nf = 0; nf < 16; nf++) {
            rm0 = fmaxf(rm0, fmaxf(sacc[nf][0], sacc[nf][1]));
            rm1 = fmaxf(rm1, fmaxf(sacc[nf][2], sacc[nf][3]));
        }
        rm0 = fmaxf(rm0, __shfl_xor_sync(0xffffffffu, rm0, 1));
        rm0 = fmaxf(rm0, __shfl_xor_sync(0xffffffffu, rm0, 2));
        rm1 = fmaxf(rm1, __shfl_xor_sync(0xffffffffu, rm1, 1));
        rm1 = fmaxf(rm1, __shfl_xor_sync(0xffffffffu, rm1, 2));

        float mn0 = fmaxf(m_[0], rm0), mn1 = fmaxf(m_[1], rm1);
        float sc0 = __expf(m_[0] - mn0), sc1 = __expf(m_[1] - mn1);
        m_[0] = mn0; m_[1] = mn1;

        float rs0 = 0.f, rs1 = 0.f;
        #pragma unroll
        for (int nf = 0; nf < 16; nf++) {
            sacc[nf][0] = __expf(sacc[nf][0] - mn0);
            sacc[nf][1] = __expf(sacc[nf][1] - mn0);
            sacc[nf][2] = __expf(sacc[nf][2] - mn1);
            sacc[nf][3] = __expf(sacc[nf][3] - mn1);
            rs0 += sacc[nf][0] + sacc[nf][1];
            rs1 += sacc[nf][2] + sacc[nf][3];
        }
        rs0 += __shfl_xor_sync(0xffffffffu, rs0, 1);
        rs0 += __shfl_xor_sync(0xffffffffu, rs0, 2);
        rs1 += __shfl_xor_sync(0xffffffffu, rs1, 1);
        rs1 += __shfl_xor_sync(0xffffffffu, rs1, 2);
        l_[0] = l_[0] * sc0 + rs0;
        l_[1] = l_[1] * sc1 + rs1;

        #pragma unroll
        for (int nf = 0; nf < 8; nf++) {
            oacc[nf][0] *= sc0; oacc[nf][1] *= sc0;
            oacc[nf][2] *= sc1; oacc[nf][3] *= sc1;
        }

        // ---- P -> smem (fp16, own 16-row band only) ----
        {
            __half* Pw = smh + PS_OFFH + (warp * 16 + g) * QSTH;
            #pragma unroll
            for (int nf = 0; nf < 16; nf++) {
                int c = nf * 8 + 2 * tg;
                *(half2*)(Pw + c) =
                    __float22half2_rn(make_float2(sacc[nf][0], sacc[nf][1]));
                *(half2*)(Pw + 8 * QSTH + c) =
                    __float22half2_rn(make_float2(sacc[nf][2], sacc[nf][3]));
            }
        }
        __syncwarp();

        // ---- O += P @ V : 16 x 64, k = 128, V frags via ldmatrix.trans ----
        const __half* Pr = smh + PS_OFFH + (warp * 16 + g) * QSTH;
        #pragma unroll
        for (int kc = 0; kc < 8; kc++) {
            uint32_t afr[4];
            const __half* ap = Pr + kc * 16 + 2 * tg;
            afr[0] = *(const uint32_t*)(ap);
            afr[1] = *(const uint32_t*)(ap + 8 * QSTH);
            afr[2] = *(const uint32_t*)(ap + 8);
            afr[3] = *(const uint32_t*)(ap + 8 * QSTH + 8);
            int vrow = kc * 16 + (lane & 15);
            #pragma unroll
            for (int nf = 0; nf < 8; nf++) {
                uint32_t saddr = vs_u32 + (uint32_t)(vrow * VSTH + nf * 8) * 2u;
                uint32_t bfr0, bfr1;
                ldmx2t(bfr0, bfr1, saddr);
                uint32_t bfr[2] = {bfr0, bfr1};
                mma_f16(oacc[nf], afr, bfr);
            }
        }
    }

    float inv0 = 1.0f / l_[0], inv1 = 1.0f / l_[1];
    int r0 = m0 + warp * 16 + g;
    #pragma unroll
    for (int nf = 0; nf < 8; nf++) {
        int c = nf * 8 + 2 * tg;
        __half* o0 = Op + (long long)r0 * EE + c;
        __half* o1 = Op + (long long)(r0 + 8) * EE + c;
        *(half2*)o0 = __float22half2_rn(make_float2(oacc[nf][0] * inv0, oacc[nf][1] * inv0));
        *(half2*)o1 = __float22half2_rn(make_float2(oacc[nf][2] * inv1, oacc[nf][3] * inv1));
    }
}

// ---------------------------------------------------------------------------
// fp16 tensor-core GEMM (validated R11): C = epi( A[M,K]h @ B[N,K]h^T ),
// fp32 accumulate. BM=128, BN=128, BK=32, 3-stage cp.async, warp tile 64x32.
// epi: 0=store f32  1=gelu(acc+bias)->half  2=C+=acc+bias (f32)
//      3=C+=acc (f32)  4=store half
// ---------------------------------------------------------------------------
#define BM 128
#define BN 128
#define BK 32
#define ASTH 40
#define NSTG 3

__global__ __launch_bounds__(256, 2) void gemm_f16(
    const __half* __restrict__ A, const __half* __restrict__ Bm,
    const float* __restrict__ bias, void* __restrict__ Cv,
    int M, int N, int K, int lda, int ldb, int ldc,
    int epi, int rnd)
{
    constexpr int ASZ = BM * ASTH;
    constexpr int BSZ = BN * ASTH;
    constexpr int ST  = ASZ + BSZ;

    extern __shared__ __half smh[];

    int m0 = blockIdx.x * BM;
    int n0 = blockIdx.y * BN;
    int nt = K / BK;

    int tid  = threadIdx.x;
    int warp = tid >> 5, lane = tid & 31;
    int g  = lane >> 2;
    int tg = lane & 3;
    int warp_m = warp >> 2;
    int warp_n = warp & 3;

    uint32_t smem_u32 = (uint32_t)__cvta_generic_to_shared(smh);

    auto load_tiles = [&](int st, int k0) {
        uint32_t sb = smem_u32 + (uint32_t)(st * ST) * 2u;
        #pragma unroll
        for (int i = 0; i < 2; i++) {
            int idx = tid + i * 256;
            int row = idx >> 2;
            int kc  = (idx & 3) << 3;
            cpa16(sb + (uint32_t)(row * ASTH + kc) * 2u,
                  A + (long long)(m0 + row) * lda + k0 + kc);
        }
        #pragma unroll
        for (int i = 0; i < 2; i++) {
            int idx = tid + i * 256;
            int row = idx >> 2;
            int kc  = (idx & 3) << 3;
            cpa16(sb + (uint32_t)(ASZ + row * ASTH + kc) * 2u,
                  Bm + (long long)(n0 + row) * ldb + k0 + kc);
        }
    };

    float acc[4][4][4];
    #pragma unroll
    for (int i = 0; i < 4; i++)
        #pragma unroll
        for (int j = 0; j < 4; j++)
            #pragma unroll
            for (int c = 0; c < 4; c++) acc[i][j][c] = 0.f;

    load_tiles(0, 0);
    cpa_commit();
    if (nt > 1) load_tiles(1, BK);
    cpa_commit();

    int cs = 0, ps = 2;
    for (int it = 0; it < nt; it++) {
        cpa_wait<1>();
        __syncthreads();
        if (it + 2 < nt) load_tiles(ps, (it + 2) * BK);
        cpa_commit();

        const __half* Ab = smh + cs * ST;
        const __half* Bb = Ab + ASZ;

        #pragma unroll
        for (int ks = 0; ks < BK; ks += 16) {
            uint32_t afr[4][4];
            #pragma unroll
            for (int mi = 0; mi < 4; mi++) {
                const __half* ap = Ab + (warp_m * 64 + mi * 16 + g) * ASTH + ks + 2 * tg;
                afr[mi][0] = *(const uint32_t*)(ap);
                afr[mi][1] = *(const uint32_t*)(ap + 8 * ASTH);
                afr[mi][2] = *(const uint32_t*)(ap + 8);
                afr[mi][3] = *(const uint32_t*)(ap + 8 * ASTH + 8);
            }
            #pragma unroll
            for (int ni = 0; ni < 4; ni++) {
                const __half* bp = Bb + (warp_n * 32 + ni * 8 + g) * ASTH + ks + 2 * tg;
                uint32_t bfr[2];
                bfr[0] = *(const uint32_t*)(bp);
                bfr[1] = *(const uint32_t*)(bp + 8);
                #pragma unroll
                for (int mi = 0; mi < 4; mi++)
                    mma_f16(acc[mi][ni], afr[mi], bfr);
            }
        }

        cs++; if (cs == NSTG) cs = 0;
        ps++; if (ps == NSTG) ps = 0;
    }

    #pragma unroll
    for (int mi = 0; mi < 4; mi++) {
        #pragma unroll
        for (int ni = 0; ni < 4; ni++) {
            int r0 = m0 + warp_m * 64 + mi * 16 + g;
            int c0 = n0 + warp_n * 32 + ni * 8 + 2 * tg;
            #pragma unroll
            for (int p = 0; p < 2; p++) {
                int m = r0 + p * 8;
                float vx = acc[mi][ni][2 * p];
                float vy = acc[mi][ni][2 * p + 1];
                if (epi == 1) {
                    vx = fast_gelu(vx + bias[c0]);
                    vy = fast_gelu(vy + bias[c0 + 1]);
                    __half* cp = (__half*)Cv + (long long)m * ldc + c0;
                    *(half2*)cp = __float22half2_rn(make_float2(vx, vy));
                } else if (epi == 4) {
                    __half* cp = (__half*)Cv + (long long)m * ldc + c0;
                    *(half2*)cp = __float22half2_rn(make_float2(vx, vy));
                } else {
                    float* cp = (float*)Cv + (long long)m * ldc + c0;
                    if (epi == 2) {
                        float2 old = *(const float2*)cp;
                        vx += bias[c0]     + old.x;
                        vy += bias[c0 + 1] + old.y;
                    } else if (epi == 3) {
                        float2 old = *(const float2*)cp;
                        vx += old.x;
                        vy += old.y;
                    }
                    if (rnd) { vx = tf32r(vx); vy = tf32r(vy); }
                    *(float2*)cp = make_float2(vx, vy);
                }
            }
        }
    }
}

// ---------------------------------------------------------------------------
// Host-side launch helper
// ---------------------------------------------------------------------------
static inline void gemm(const __half* A, const __half* B, const float* bias, void* C,
                        int M, int N, int K, int lda, int ldb, int ldc,
                        int epi, int rnd)
{
    dim3 block(256);
    dim3 grid(M / BM, N / BN);
    size_t bytes = (size_t)NSTG * (BM * ASTH + BN * ASTH) * 2;
    gemm_f16<<<grid, block, bytes>>>(A, B, bias, C, M, N, K, lda, ldb, ldc, epi, rnd);
}

extern "C" void kernel_launch(void* const* d_in, const int* in_sizes, int n_in,
                              void* d_out, int out_size)
{
    (void)in_sizes; (void)n_in; (void)out_size;
    const int*   idx  = (const int*)  d_in[0];
    const float* wte  = (const float*)d_in[1];
    const float* wpe  = (const float*)d_in[2];
    const float* Wq   = (const float*)d_in[3];
    const float* Wk   = (const float*)d_in[4];
    const float* Wv   = (const float*)d_in[5];
    const float* Wo   = (const float*)d_in[6];
    const float* ln1g = (const float*)d_in[7];
    const float* ln1b = (const float*)d_in[8];
    const float* ln2g = (const float*)d_in[9];
    const float* ln2b = (const float*)d_in[10];
    const float* W1   = (const float*)d_in[11];
    const float* b1   = (const float*)d_in[12];
    const float* W2   = (const float*)d_in[13];
    const float* b2   = (const float*)d_in[14];
    const float* lnfg = (const float*)d_in[15];
    const float* lnfb = (const float*)d_in[16];
    float* out = (float*)d_out;

    float *x;
    __half *h, *qkv, *o, *f, *wqkv, *wo, *w1, *w2, *wt;
    cudaGetSymbolAddress((void**)&x, g_x);
    cudaGetSymbolAddress((void**)&h, g_h);
    cudaGetSymbolAddress((void**)&qkv, g_qkv);
    cudaGetSymbolAddress((void**)&o, g_o);
    cudaGetSymbolAddress((void**)&f, g_f);
    cudaGetSymbolAddress((void**)&wqkv, g_wqkv);
    cudaGetSymbolAddress((void**)&wo, g_wo);
    cudaGetSymbolAddress((void**)&w1, g_w1);
    cudaGetSymbolAddress((void**)&w2, g_w2);
    cudaGetSymbolAddress((void**)&wt, g_wte);

    cudaFuncSetAttribute(gemm_f16, cudaFuncAttributeMaxDynamicSharedMemorySize, 64 * 1024);
    cudaFuncSetAttribute(flash_kernel, cudaFuncAttributeMaxDynamicSharedMemorySize, FA_SMEM);

    // weight prep: transpose + fp16 convert
    {
        dim3 blk(256);
        transpose_qkv<<<dim3(QKVW / 32, EE / 32, LL), blk>>>(Wq, Wk, Wv, wqkv);
        transpose_half<<<dim3(EE / 32, EE / 32, LL), blk>>>(Wo, wo, EE, EE);
        transpose_half<<<dim3(FF / 32, EE / 32, LL), blk>>>(W1, w1, EE, FF);
        transpose_half<<<dim3(EE / 32, FF / 32, LL), blk>>>(W2, w2, FF, EE);
        long long n2 = (long long)VV * EE / 2;
        conv_half<<<(unsigned)((n2 + 255) / 256), blk>>>(wte, wt, n2);
    }

    embed_kernel<<<(MM * EE) / 256, 256>>>(idx, wte, wpe, x);

    for (int l = 0; l < LL; l++) {
        ln_kernel<<<MM, 256>>>(x, ln1g + (long long)l * EE, ln1b + (long long)l * EE, h);

        // fused QKV projection -> fp16 qkv
        gemm(h, wqkv + (long long)l * QKVW * EE, nullptr, qkv,
             MM, QKVW, EE, EE, EE, QKVW, 4, 0);

        // fused causal attention (fp16) -> fp16 o
        {
            dim3 grid(TT / 128, BB * HH);
            flash_kernel<<<grid, 256, FA_SMEM>>>(qkv, o);
        }

        // x += o @ Wo^T
        gemm(o, wo + (long long)l * EE * EE, nullptr, x,
             MM, EE, EE, EE, EE, EE, 3, 0);

        ln_kernel<<<MM, 256>>>(x, ln2g + (long long)l * EE, ln2b + (long long)l * EE, h);

        // f = gelu(h @ W1 + b1) -> fp16
        gemm(h, w1 + (long long)l * FF * EE, b1 + (long long)l * FF, f,
             MM, FF, EE, EE, EE, FF, 1, 0);

        // x += f @ W2 + b2
        gemm(f, w2 + (long long)l * EE * FF, b2 + (long long)l * EE, x,
             MM, EE, FF, FF, FF, EE, 2, 0);
    }

    ln_kernel<<<MM, 256>>>(x, lnfg, lnfb, h);

    // logits = h @ wte^T
    gemm(h, wt, nullptr, out, MM, VV, EE, EE, EE, VV, 0, 0);
}